// round 4
// baseline (speedup 1.0000x reference)
#include <cuda_runtime.h>
#include <cuda_bf16.h>
#include <math.h>
#include <stdint.h>

// Problem constants
#define L_DIM   2048
#define E_DIM   512
#define EPT_DIM 300
#define H_DIM   16
#define KBIG    (H_DIM * EPT_DIM)   // 4800

// Scratch (allocation-free rule: __device__ globals)
__device__ float          g_Z  [L_DIM * KBIG];   // fp32 Z (for exact fixup)
__device__ __nv_bfloat16  g_Zhi[L_DIM * KBIG];
__device__ __nv_bfloat16  g_Zlo[L_DIM * KBIG];
__device__ float g_S [L_DIM * L_DIM];
__device__ float g_T0[L_DIM * E_DIM];
__device__ float g_X1[L_DIM * E_DIM];
__device__ float g_T1[L_DIM * E_DIM];

#define MAXB (1 << 18)
__device__ int  g_cnt;
__device__ int2 g_list[MAXB];

// ===========================================================================
// Helpers: portable (non-'a') tensor-core path — ldmatrix + mma.sync + cp.async
// ===========================================================================
__device__ __forceinline__ uint32_t smem_u32(const void* p) {
    uint32_t a;
    asm("{ .reg .u64 t; cvta.to.shared.u64 t, %1; cvt.u32.u64 %0, t; }"
        : "=r"(a) : "l"(p));
    return a;
}
__device__ __forceinline__ void ldsm_x4(uint32_t* r, uint32_t addr) {
    asm volatile("ldmatrix.sync.aligned.m8n8.x4.shared.b16 {%0,%1,%2,%3}, [%4];"
                 : "=r"(r[0]), "=r"(r[1]), "=r"(r[2]), "=r"(r[3]) : "r"(addr));
}
__device__ __forceinline__ void ldsm_x2(uint32_t* r, uint32_t addr) {
    asm volatile("ldmatrix.sync.aligned.m8n8.x2.shared.b16 {%0,%1}, [%2];"
                 : "=r"(r[0]), "=r"(r[1]) : "r"(addr));
}
__device__ __forceinline__ void mma_bf16(float* d, const uint32_t* a,
                                         const uint32_t* b) {
    asm volatile("mma.sync.aligned.m16n8k16.row.col.f32.bf16.bf16.f32 "
                 "{%0,%1,%2,%3}, {%4,%5,%6,%7}, {%8,%9}, {%0,%1,%2,%3};"
                 : "+f"(d[0]), "+f"(d[1]), "+f"(d[2]), "+f"(d[3])
                 : "r"(a[0]), "r"(a[1]), "r"(a[2]), "r"(a[3]),
                   "r"(b[0]), "r"(b[1]));
}
#define CP_ASYNC16(dst, src) \
    asm volatile("cp.async.cg.shared.global [%0], [%1], 16;" \
                 :: "r"(dst), "l"(src))
#define CP_COMMIT()  asm volatile("cp.async.commit_group;" ::: "memory")
#define CP_WAIT(N)   asm volatile("cp.async.wait_group " #N ";" ::: "memory")

#define SW128(x) ((x) ^ (((x) >> 3) & 0x70))

// ===========================================================================
// Kernel 1: Z (fp32) + bf16 hi/lo split
// ===========================================================================
__global__ __launch_bounds__(256) void compute_z(
    const float* __restrict__ xpt, const float* __restrict__ Wpt,
    float* __restrict__ Z, __nv_bfloat16* __restrict__ Zhi,
    __nv_bfloat16* __restrict__ Zlo)
{
    const int l   = blockIdx.x;
    const int tid = threadIdx.x;
    __shared__ float sx[EPT_DIM];
    __shared__ float red[8];

    for (int e = tid; e < EPT_DIM; e += 256) sx[e] = xpt[(size_t)l * EPT_DIM + e];
    __syncthreads();

    const int e0 = tid, e1 = tid + 256;
    for (int h = 0; h < H_DIM; h++) {
        float v0 = 0.f, v1 = 0.f;
        if (e0 < EPT_DIM) { float w = Wpt[h * EPT_DIM + e0]; v0 = sx[e0] * w * w; }
        if (e1 < EPT_DIM) { float w = Wpt[h * EPT_DIM + e1]; v1 = sx[e1] * w * w; }
        float ss = v0 * v0 + v1 * v1;
        #pragma unroll
        for (int o = 16; o; o >>= 1) ss += __shfl_xor_sync(0xffffffffu, ss, o);
        if ((tid & 31) == 0) red[tid >> 5] = ss;
        __syncthreads();
        float tot = red[0] + red[1] + red[2] + red[3] +
                    red[4] + red[5] + red[6] + red[7];
        float inv = 0.25f / fmaxf(sqrtf(tot), 1e-12f);
        size_t base = (size_t)l * KBIG + h * EPT_DIM;
        if (e0 < EPT_DIM) {
            float v = v0 * inv;
            __nv_bfloat16 hb = __float2bfloat16(v);
            Z[base + e0] = v; Zhi[base + e0] = hb;
            Zlo[base + e0] = __float2bfloat16(v - __bfloat162float(hb));
        }
        if (e1 < EPT_DIM) {
            float v = v1 * inv;
            __nv_bfloat16 hb = __float2bfloat16(v);
            Z[base + e1] = v; Zhi[base + e1] = hb;
            Zlo[base + e1] = __float2bfloat16(v - __bfloat162float(hb));
        }
        __syncthreads();
    }
}

// ===========================================================================
// Kernel 2: ZZ^T via warp-level mma.sync (bf16 3-pass hi/lo split), symmetric.
// 128x128 CTA tile, BK=64 (one SW128 row), 8 warps (2x4), warp tile 64x32.
// smem parts per stage: 0=Ahi 1=Alo 2=Bhi 3=Blo, each 128 rows x 128B = 16KB.
// ===========================================================================
#define TILE_B 16384
#define STOFF(s, p) ((s) * 4 * TILE_B + (p) * TILE_B)
#define ZZT_SMEM (8 * TILE_B + 128)

__global__ void __launch_bounds__(256, 1) zzt_mma(
    const __nv_bfloat16* __restrict__ Zhi,
    const __nv_bfloat16* __restrict__ Zlo,
    float* __restrict__ S)
{
    const int bx = blockIdx.x, by = blockIdx.y;
    if (bx < by) return;
    extern __shared__ char smem_raw[];
    const uint32_t sb = (smem_u32(smem_raw) + 127u) & ~127u;

    const int tid  = threadIdx.x;
    const int wid  = tid >> 5, lane = tid & 31;
    const int bm = by << 7, bn = bx << 7;
    const int wm = wid >> 2, wn = wid & 3;     // 2 x 4 warp grid

    float acc[4][4][4];
    #pragma unroll
    for (int mt = 0; mt < 4; mt++)
        #pragma unroll
        for (int nt = 0; nt < 4; nt++)
            #pragma unroll
            for (int f = 0; f < 4; f++) acc[mt][nt][f] = 0.f;

    // stage loader via cp.async: 4 parts x 1024 16B-chunks, 4 chunks/thread/part
    auto cp_stage = [&](int s, int kt) {
        const int k0 = kt << 6;
        #pragma unroll
        for (int p = 0; p < 4; p++) {
            const __nv_bfloat16* g = (p & 1) ? Zlo : Zhi;
            const int rb = (p < 2) ? bm : bn;
            #pragma unroll
            for (int t = 0; t < 4; t++) {
                int idx = tid + t * 256;
                int r = idx >> 3, ch = idx & 7;
                uint32_t dst = sb + STOFF(s, p) + SW128(r * 128 + ch * 16);
                const void* src = g + (size_t)(rb + r) * KBIG + k0 + ch * 8;
                CP_ASYNC16(dst, src);
            }
        }
        CP_COMMIT();
    };

    auto compute = [&](int s) {
        const uint32_t b_ahi = sb + STOFF(s, 0), b_alo = sb + STOFF(s, 1);
        const uint32_t b_bhi = sb + STOFF(s, 2), b_blo = sb + STOFF(s, 3);
        #pragma unroll
        for (int ks = 0; ks < 4; ks++) {
            uint32_t ahi[4][4], alo[4][4], bhi[4][2], blo[4][2];
            #pragma unroll
            for (int mt = 0; mt < 4; mt++) {
                int r  = wm * 64 + mt * 16 + (lane & 15);
                int ch = ks * 2 + (lane >> 4);
                uint32_t a = SW128(r * 128 + ch * 16);
                ldsm_x4(ahi[mt], b_ahi + a);
                ldsm_x4(alo[mt], b_alo + a);
            }
            #pragma unroll
            for (int nt = 0; nt < 4; nt++) {
                int r  = wn * 32 + nt * 8 + (lane & 7);
                int ch = ks * 2 + ((lane >> 3) & 1);
                uint32_t a = SW128(r * 128 + ch * 16);
                ldsm_x2(bhi[nt], b_bhi + a);
                ldsm_x2(blo[nt], b_blo + a);
            }
            #pragma unroll
            for (int mt = 0; mt < 4; mt++)
                #pragma unroll
                for (int nt = 0; nt < 4; nt++) {
                    mma_bf16(acc[mt][nt], ahi[mt], bhi[nt]);
                    mma_bf16(acc[mt][nt], ahi[mt], blo[nt]);
                    mma_bf16(acc[mt][nt], alo[mt], bhi[nt]);
                }
        }
    };

    const int NKT = KBIG / 64;   // 75
    cp_stage(0, 0);
    for (int kt = 0; kt < NKT; kt++) {
        if (kt + 1 < NKT) {
            cp_stage((kt + 1) & 1, kt + 1);
            CP_WAIT(1);
        } else {
            CP_WAIT(0);
        }
        __syncthreads();
        compute(kt & 1);
        __syncthreads();
    }

    // epilogue: direct + transposed tile stores
    #pragma unroll
    for (int mt = 0; mt < 4; mt++)
        #pragma unroll
        for (int nt = 0; nt < 4; nt++) {
            const int r0 = bm + wm * 64 + mt * 16 + (lane >> 2);
            const int c0 = bn + wn * 32 + nt * 8 + (lane & 3) * 2;
            const float* d = acc[mt][nt];
            *(float2*)(S + (size_t)r0 * L_DIM + c0)       = make_float2(d[0], d[1]);
            *(float2*)(S + (size_t)(r0 + 8) * L_DIM + c0) = make_float2(d[2], d[3]);
            if (bx != by) {
                S[(size_t)c0 * L_DIM + r0]           = d[0];
                S[(size_t)(c0 + 1) * L_DIM + r0]     = d[1];
                S[(size_t)c0 * L_DIM + r0 + 8]       = d[2];
                S[(size_t)(c0 + 1) * L_DIM + r0 + 8] = d[3];
            }
        }
}

// ===========================================================================
// Fixup: exact fp32 recompute of near-threshold scores
// ===========================================================================
__global__ void zero_cnt() { g_cnt = 0; }

__global__ __launch_bounds__(256) void scan_band(const float* __restrict__ S)
{
    const int n = L_DIM * L_DIM;
    for (int i = blockIdx.x * 256 + threadIdx.x; i < n; i += gridDim.x * 256) {
        float s = S[i];
        if (fabsf(s - 0.1f) < 3e-4f) {
            int p = atomicAdd(&g_cnt, 1);
            if (p < MAXB) g_list[p] = make_int2(i >> 11, i & (L_DIM - 1));
        }
    }
}

__global__ __launch_bounds__(256) void fixup_band(
    const float* __restrict__ Z, float* __restrict__ S)
{
    const int wglobal = blockIdx.x * 8 + (threadIdx.x >> 5);
    const int lid = threadIdx.x & 31;
    const int nw = gridDim.x * 8;
    int cnt = g_cnt; if (cnt > MAXB) cnt = MAXB;
    for (int e = wglobal; e < cnt; e += nw) {
        int2 ij = g_list[e];
        const float* a = Z + (size_t)ij.x * KBIG;
        const float* b = Z + (size_t)ij.y * KBIG;
        float sum = 0.f;
        for (int k = lid; k < KBIG; k += 32) sum = fmaf(a[k], b[k], sum);
        #pragma unroll
        for (int o = 16; o; o >>= 1) sum += __shfl_xor_sync(0xffffffffu, sum, o);
        if (lid == 0) S[(size_t)ij.x * L_DIM + ij.y] = sum;
    }
}

// ===========================================================================
// SIMT double-buffered GEMM (GCN layers)
// ===========================================================================
template <int BM, int BN, int TRANS_B, int RELU>
__global__ __launch_bounds__(256, 1) void gemm_db(
    const float* __restrict__ A, const float* __restrict__ B,
    float* __restrict__ C, int M, int N, int K)
{
    constexpr int TM = BM / 16;
    constexpr int TN = BN / 16;
    constexpr int NA = BM / 64;
    constexpr int NB = (16 * BN) / 1024;

    __shared__ float As[2][16][BM + 4];
    __shared__ float Bs[2][16][BN + 4];

    const int bm = blockIdx.y * BM;
    const int bn = blockIdx.x * BN;
    const int tid = threadIdx.x;
    const int tx  = tid & 15;
    const int ty  = tid >> 4;

    float acc[TM][TN];
    #pragma unroll
    for (int i = 0; i < TM; i++)
        #pragma unroll
        for (int j = 0; j < TN; j++) acc[i][j] = 0.f;

    float4 ra[NA], rb[NB];

    #define LD_A(k0)                                                          \
        _Pragma("unroll")                                                     \
        for (int t = 0; t < NA; t++) {                                        \
            int idx = tid + t * 256;                                          \
            int rr = idx >> 2, cc = (idx & 3) << 2;                           \
            ra[t] = *(const float4*)(A + (size_t)(bm + rr) * K + (k0) + cc);  \
        }
    #define LD_B(k0)                                                          \
        _Pragma("unroll")                                                     \
        for (int t = 0; t < NB; t++) {                                        \
            int idx = tid + t * 256;                                          \
            if (TRANS_B) {                                                    \
                int rr = idx >> 2, cc = (idx & 3) << 2;                       \
                rb[t] = *(const float4*)(B + (size_t)(bn + rr) * K + (k0) + cc); \
            } else {                                                          \
                int rr = idx / (BN / 4), cc = (idx % (BN / 4)) << 2;          \
                rb[t] = *(const float4*)(B + (size_t)((k0) + rr) * N + bn + cc); \
            }                                                                 \
        }
    #define ST_A(buf)                                                         \
        _Pragma("unroll")                                                     \
        for (int t = 0; t < NA; t++) {                                        \
            int idx = tid + t * 256;                                          \
            int rr = idx >> 2, cc = (idx & 3) << 2;                           \
            As[buf][cc + 0][rr] = ra[t].x; As[buf][cc + 1][rr] = ra[t].y;     \
            As[buf][cc + 2][rr] = ra[t].z; As[buf][cc + 3][rr] = ra[t].w;     \
        }
    #define ST_B(buf)                                                         \
        _Pragma("unroll")                                                     \
        for (int t = 0; t < NB; t++) {                                        \
            int idx = tid + t * 256;                                          \
            if (TRANS_B) {                                                    \
                int rr = idx >> 2, cc = (idx & 3) << 2;                       \
                Bs[buf][cc + 0][rr] = rb[t].x; Bs[buf][cc + 1][rr] = rb[t].y; \
                Bs[buf][cc + 2][rr] = rb[t].z; Bs[buf][cc + 3][rr] = rb[t].w; \
            } else {                                                          \
                int rr = idx / (BN / 4), cc = (idx % (BN / 4)) << 2;          \
                *(float4*)&Bs[buf][rr][cc] = rb[t];                           \
            }                                                                 \
        }

    const int nk = K >> 4;
    LD_A(0); LD_B(0);
    ST_A(0); ST_B(0);
    __syncthreads();

    int cur = 0;
    for (int kt = 0; kt < nk; kt++) {
        if (kt + 1 < nk) { int k0 = (kt + 1) << 4; LD_A(k0); LD_B(k0); }
        #pragma unroll
        for (int kk = 0; kk < 16; kk++) {
            float a[TM], b[TN];
            #pragma unroll
            for (int i = 0; i < TM; i += 4)
                *(float4*)(a + i) = *(const float4*)&As[cur][kk][ty * TM + i];
            #pragma unroll
            for (int j = 0; j < TN; j += 4)
                *(float4*)(b + j) = *(const float4*)&Bs[cur][kk][tx * TN + j];
            #pragma unroll
            for (int i = 0; i < TM; i++)
                #pragma unroll
                for (int j = 0; j < TN; j++)
                    acc[i][j] = fmaf(a[i], b[j], acc[i][j]);
        }
        if (kt + 1 < nk) { ST_A(cur ^ 1); ST_B(cur ^ 1); }
        __syncthreads();
        cur ^= 1;
    }

    #pragma unroll
    for (int i = 0; i < TM; i++) {
        float* crow = C + (size_t)(bm + ty * TM + i) * N + bn + tx * TN;
        #pragma unroll
        for (int j = 0; j < TN; j += 4) {
            float4 v;
            v.x = acc[i][j + 0]; v.y = acc[i][j + 1];
            v.z = acc[i][j + 2]; v.w = acc[i][j + 3];
            if (RELU) {
                v.x = fmaxf(v.x, 0.f); v.y = fmaxf(v.y, 0.f);
                v.z = fmaxf(v.z, 0.f); v.w = fmaxf(v.w, 0.f);
            }
            *(float4*)(crow + j) = v;
        }
    }
    #undef LD_A
    #undef LD_B
    #undef ST_A
    #undef ST_B
}

// ===========================================================================
// Masked softmax
// ===========================================================================
__global__ __launch_bounds__(256) void masked_softmax(float* __restrict__ S)
{
    __shared__ float red[8];
    const int r   = blockIdx.x;
    const int tid = threadIdx.x;
    float* row = S + (size_t)r * L_DIM;

    float m = -1e30f;
    for (int c = tid; c < L_DIM; c += 256) {
        float s = row[c];
        if (s >= 0.1f) m = fmaxf(m, s);
    }
    #pragma unroll
    for (int o = 16; o; o >>= 1) m = fmaxf(m, __shfl_xor_sync(0xffffffffu, m, o));
    if ((tid & 31) == 0) red[tid >> 5] = m;
    __syncthreads();
    float M = fmaxf(fmaxf(fmaxf(red[0], red[1]), fmaxf(red[2], red[3])),
                    fmaxf(fmaxf(red[4], red[5]), fmaxf(red[6], red[7])));
    __syncthreads();

    float sum = 0.f;
    for (int c = tid; c < L_DIM; c += 256) {
        float s = row[c];
        float e = (s >= 0.1f) ? expf(s - M) : 0.f;
        row[c] = e;
        sum += e;
    }
    #pragma unroll
    for (int o = 16; o; o >>= 1) sum += __shfl_xor_sync(0xffffffffu, sum, o);
    if ((tid & 31) == 0) red[tid >> 5] = sum;
    __syncthreads();
    float T = red[0] + red[1] + red[2] + red[3] +
              red[4] + red[5] + red[6] + red[7];
    float inv = 1.f / T;
    for (int c = tid; c < L_DIM; c += 256) row[c] *= inv;
}

// ===========================================================================
// Launch
// ===========================================================================
extern "C" void kernel_launch(void* const* d_in, const int* in_sizes, int n_in,
                              void* d_out, int out_size)
{
    const float* Lemb = (const float*)d_in[0];
    const float* Xpt  = (const float*)d_in[1];
    const float* Wpt  = (const float*)d_in[2];
    const float* W0   = (const float*)d_in[3];
    const float* W1   = (const float*)d_in[4];
    float* out = (float*)d_out;

    float *Z, *S, *T0, *X1, *T1;
    __nv_bfloat16 *Zhi, *Zlo;
    cudaGetSymbolAddress((void**)&Z,   g_Z);
    cudaGetSymbolAddress((void**)&Zhi, g_Zhi);
    cudaGetSymbolAddress((void**)&Zlo, g_Zlo);
    cudaGetSymbolAddress((void**)&S,   g_S);
    cudaGetSymbolAddress((void**)&T0,  g_T0);
    cudaGetSymbolAddress((void**)&X1,  g_X1);
    cudaGetSymbolAddress((void**)&T1,  g_T1);

    cudaFuncSetAttribute(zzt_mma, cudaFuncAttributeMaxDynamicSharedMemorySize,
                         ZZT_SMEM);

    // 1) Z + bf16 split
    compute_z<<<L_DIM, 256>>>(Xpt, Wpt, Z, Zhi, Zlo);

    // 2) scores = Z Z^T via warp mma.sync (3-pass bf16 split), symmetric
    zzt_mma<<<dim3(16, 16), 256, ZZT_SMEM>>>(Zhi, Zlo, S);

    // 3) exact fp32 fixup of near-threshold entries
    zero_cnt<<<1, 1>>>();
    scan_band<<<1024, 256>>>(S);
    fixup_band<<<512, 256>>>(Z, S);

    // 4) adj = softmax(threshold(scores))
    masked_softmax<<<L_DIM, 256>>>(S);

    // 5-8) GCN layers (SIMT fp32)
    gemm_db<128, 64, 0, 0><<<dim3(E_DIM / 64, L_DIM / 128), 256>>>(
        Lemb, W0, T0, L_DIM, E_DIM, E_DIM);
    gemm_db<128, 64, 0, 1><<<dim3(E_DIM / 64, L_DIM / 128), 256>>>(
        S, T0, X1, L_DIM, E_DIM, L_DIM);
    gemm_db<128, 64, 0, 0><<<dim3(E_DIM / 64, L_DIM / 128), 256>>>(
        X1, W1, T1, L_DIM, E_DIM, E_DIM);
    gemm_db<128, 64, 0, 1><<<dim3(E_DIM / 64, L_DIM / 128), 256>>>(
        S, T1, out, L_DIM, E_DIM, L_DIM);
}

// round 5
// speedup vs baseline: 1.5860x; 1.5860x over previous
#include <cuda_runtime.h>
#include <cuda_bf16.h>
#include <math.h>
#include <stdint.h>

// Problem constants
#define L_DIM   2048
#define E_DIM   512
#define EPT_DIM 300
#define H_DIM   16
#define KBIG    (H_DIM * EPT_DIM)   // 4800

// Scratch (allocation-free rule: __device__ globals)
__device__ float          g_Z  [L_DIM * KBIG];   // fp32 Z (for exact fixup)
__device__ __nv_bfloat16  g_Zhi[L_DIM * KBIG];
__device__ __nv_bfloat16  g_Zlo[L_DIM * KBIG];
__device__ float g_S [L_DIM * L_DIM];
__device__ float g_T0[L_DIM * E_DIM];
__device__ float g_X1[L_DIM * E_DIM];
__device__ float g_T1[L_DIM * E_DIM];

#define MAXB (1 << 18)
__device__ int  g_cnt;
__device__ int2 g_list[MAXB];

// ===========================================================================
// Helpers: portable tensor-core path — ldmatrix + mma.sync + cp.async
// ===========================================================================
__device__ __forceinline__ uint32_t smem_u32(const void* p) {
    uint32_t a;
    asm("{ .reg .u64 t; cvta.to.shared.u64 t, %1; cvt.u32.u64 %0, t; }"
        : "=r"(a) : "l"(p));
    return a;
}
__device__ __forceinline__ void ldsm_x4(uint32_t* r, uint32_t addr) {
    asm volatile("ldmatrix.sync.aligned.m8n8.x4.shared.b16 {%0,%1,%2,%3}, [%4];"
                 : "=r"(r[0]), "=r"(r[1]), "=r"(r[2]), "=r"(r[3]) : "r"(addr));
}
__device__ __forceinline__ void ldsm_x2(uint32_t* r, uint32_t addr) {
    asm volatile("ldmatrix.sync.aligned.m8n8.x2.shared.b16 {%0,%1}, [%2];"
                 : "=r"(r[0]), "=r"(r[1]) : "r"(addr));
}
__device__ __forceinline__ void mma_bf16(float* d, const uint32_t* a,
                                         const uint32_t* b) {
    asm volatile("mma.sync.aligned.m16n8k16.row.col.f32.bf16.bf16.f32 "
                 "{%0,%1,%2,%3}, {%4,%5,%6,%7}, {%8,%9}, {%0,%1,%2,%3};"
                 : "+f"(d[0]), "+f"(d[1]), "+f"(d[2]), "+f"(d[3])
                 : "r"(a[0]), "r"(a[1]), "r"(a[2]), "r"(a[3]),
                   "r"(b[0]), "r"(b[1]));
}
#define CP_ASYNC16(dst, src) \
    asm volatile("cp.async.cg.shared.global [%0], [%1], 16;" \
                 :: "r"(dst), "l"(src))
#define CP_COMMIT()  asm volatile("cp.async.commit_group;" ::: "memory")
#define CP_WAIT(N)   asm volatile("cp.async.wait_group " #N ";" ::: "memory")

#define SW128(x) ((x) ^ (((x) >> 3) & 0x70))

// ===========================================================================
// Kernel 1: Z (fp32) + bf16 hi/lo split
// ===========================================================================
__global__ __launch_bounds__(256) void compute_z(
    const float* __restrict__ xpt, const float* __restrict__ Wpt,
    float* __restrict__ Z, __nv_bfloat16* __restrict__ Zhi,
    __nv_bfloat16* __restrict__ Zlo)
{
    const int l   = blockIdx.x;
    const int tid = threadIdx.x;
    __shared__ float sx[EPT_DIM];
    __shared__ float red[8];

    for (int e = tid; e < EPT_DIM; e += 256) sx[e] = xpt[(size_t)l * EPT_DIM + e];
    __syncthreads();

    const int e0 = tid, e1 = tid + 256;
    for (int h = 0; h < H_DIM; h++) {
        float v0 = 0.f, v1 = 0.f;
        if (e0 < EPT_DIM) { float w = Wpt[h * EPT_DIM + e0]; v0 = sx[e0] * w * w; }
        if (e1 < EPT_DIM) { float w = Wpt[h * EPT_DIM + e1]; v1 = sx[e1] * w * w; }
        float ss = v0 * v0 + v1 * v1;
        #pragma unroll
        for (int o = 16; o; o >>= 1) ss += __shfl_xor_sync(0xffffffffu, ss, o);
        if ((tid & 31) == 0) red[tid >> 5] = ss;
        __syncthreads();
        float tot = red[0] + red[1] + red[2] + red[3] +
                    red[4] + red[5] + red[6] + red[7];
        float inv = 0.25f / fmaxf(sqrtf(tot), 1e-12f);
        size_t base = (size_t)l * KBIG + h * EPT_DIM;
        if (e0 < EPT_DIM) {
            float v = v0 * inv;
            __nv_bfloat16 hb = __float2bfloat16(v);
            Z[base + e0] = v; Zhi[base + e0] = hb;
            Zlo[base + e0] = __float2bfloat16(v - __bfloat162float(hb));
        }
        if (e1 < EPT_DIM) {
            float v = v1 * inv;
            __nv_bfloat16 hb = __float2bfloat16(v);
            Z[base + e1] = v; Zhi[base + e1] = hb;
            Zlo[base + e1] = __float2bfloat16(v - __bfloat162float(hb));
        }
        __syncthreads();
    }
}

// ===========================================================================
// Kernel 2: ZZ^T via mma.sync, 3-stage cp.async pipeline, hoisted addressing.
// 128x128 CTA tile, BK=64, 8 warps (2x4), warp tile 64x32, 3-pass hi/lo.
// Stage layout: 4 parts (Ahi,Alo,Bhi,Blo) x 16KB. Band scan fused in epilogue.
// ===========================================================================
#define TILE_B   16384
#define STAGE_B  (4 * TILE_B)          // 64 KB
#define ZZT_SMEM (3 * STAGE_B + 128)

__global__ void __launch_bounds__(256, 1) zzt_mma(
    const __nv_bfloat16* __restrict__ Zhi,
    const __nv_bfloat16* __restrict__ Zlo,
    float* __restrict__ S)
{
    const int bx = blockIdx.x, by = blockIdx.y;
    if (bx < by) return;
    extern __shared__ char smem_raw[];
    const uint32_t sb = (smem_u32(smem_raw) + 127u) & ~127u;

    const int tid  = threadIdx.x;
    const int wid  = tid >> 5, lane = tid & 31;
    const int bm = by << 7, bn = bx << 7;
    const int wm = wid >> 2, wn = wid & 3;     // 2 x 4 warp grid

    float acc[4][4][4];
    #pragma unroll
    for (int mt = 0; mt < 4; mt++)
        #pragma unroll
        for (int nt = 0; nt < 4; nt++)
            #pragma unroll
            for (int f = 0; f < 4; f++) acc[mt][nt][f] = 0.f;

    // ---- hoisted ldmatrix offsets (within a part) -------------------------
    uint32_t offA[4][4], offB[4][4];
    #pragma unroll
    for (int mt = 0; mt < 4; mt++) {
        int r  = wm * 64 + mt * 16 + (lane & 15);
        int r7 = r & 7;
        #pragma unroll
        for (int ks = 0; ks < 4; ks++) {
            int ch = ks * 2 + (lane >> 4);
            offA[mt][ks] = r * 128 + ((ch ^ r7) << 4);
        }
    }
    #pragma unroll
    for (int nt = 0; nt < 4; nt++) {
        int r  = wn * 32 + nt * 8 + (lane & 7);
        int r7 = r & 7;
        #pragma unroll
        for (int ks = 0; ks < 4; ks++) {
            int ch = ks * 2 + ((lane >> 3) & 1);
            offB[nt][ks] = r * 128 + ((ch ^ r7) << 4);
        }
    }

    // ---- hoisted cp.async offsets -----------------------------------------
    // per t: r = (tid + t*256)>>3, ch = (tid + t*256)&7
    uint32_t dstoff[4];
    int      srcA[4], srcB[4];
    #pragma unroll
    for (int t = 0; t < 4; t++) {
        int idx = tid + t * 256;
        int r = idx >> 3, ch = idx & 7;
        dstoff[t] = (uint32_t)(r * 128 + ((ch ^ (r & 7)) << 4));
        srcA[t] = (bm + r) * KBIG + ch * 8;
        srcB[t] = (bn + r) * KBIG + ch * 8;
    }

    auto cp_stage = [&](int s, int kt) {
        const int k0 = kt << 6;
        const uint32_t base = sb + (uint32_t)s * STAGE_B;
        #pragma unroll
        for (int t = 0; t < 4; t++) {
            CP_ASYNC16(base + dstoff[t],              Zhi + srcA[t] + k0);
            CP_ASYNC16(base + TILE_B + dstoff[t],     Zlo + srcA[t] + k0);
            CP_ASYNC16(base + 2 * TILE_B + dstoff[t], Zhi + srcB[t] + k0);
            CP_ASYNC16(base + 3 * TILE_B + dstoff[t], Zlo + srcB[t] + k0);
        }
        CP_COMMIT();
    };

    auto compute = [&](int s) {
        const uint32_t pa = sb + (uint32_t)s * STAGE_B;
        #pragma unroll
        for (int ks = 0; ks < 4; ks++) {
            uint32_t ahi[4][4], alo[4][4];
            #pragma unroll
            for (int mt = 0; mt < 4; mt++) {
                ldsm_x4(ahi[mt], pa + offA[mt][ks]);
                ldsm_x4(alo[mt], pa + TILE_B + offA[mt][ks]);
            }
            #pragma unroll
            for (int nt = 0; nt < 4; nt++) {
                uint32_t bh[2], bl[2];
                ldsm_x2(bh, pa + 2 * TILE_B + offB[nt][ks]);
                ldsm_x2(bl, pa + 3 * TILE_B + offB[nt][ks]);
                #pragma unroll
                for (int mt = 0; mt < 4; mt++) {
                    mma_bf16(acc[mt][nt], ahi[mt], bh);
                    mma_bf16(acc[mt][nt], ahi[mt], bl);
                    mma_bf16(acc[mt][nt], alo[mt], bh);
                }
            }
        }
    };

    const int NKT = KBIG / 64;   // 75 (divisible by 3)
    cp_stage(0, 0);
    cp_stage(1, 1);

    int sc = 0, s2 = 2;
    for (int kt = 0; kt < NKT; kt++) {
        if (kt + 1 < NKT) { CP_WAIT(1); } else { CP_WAIT(0); }
        __syncthreads();
        if (kt + 2 < NKT) cp_stage(s2, kt + 2);
        compute(sc);
        if (++sc == 3) sc = 0;
        if (++s2 == 3) s2 = 0;
    }

    // ---- epilogue: stores + fused near-threshold band scan -----------------
    #pragma unroll
    for (int mt = 0; mt < 4; mt++)
        #pragma unroll
        for (int nt = 0; nt < 4; nt++) {
            const int r0 = bm + wm * 64 + mt * 16 + (lane >> 2);
            const int c0 = bn + wn * 32 + nt * 8 + (lane & 3) * 2;
            const float* d = acc[mt][nt];
            *(float2*)(S + (size_t)r0 * L_DIM + c0)       = make_float2(d[0], d[1]);
            *(float2*)(S + (size_t)(r0 + 8) * L_DIM + c0) = make_float2(d[2], d[3]);
            if (bx != by) {
                S[(size_t)c0 * L_DIM + r0]           = d[0];
                S[(size_t)(c0 + 1) * L_DIM + r0]     = d[1];
                S[(size_t)c0 * L_DIM + r0 + 8]       = d[2];
                S[(size_t)(c0 + 1) * L_DIM + r0 + 8] = d[3];
            }
            #pragma unroll
            for (int f = 0; f < 4; f++) {
                if (fabsf(d[f] - 0.1f) < 3e-4f) {
                    int rr = r0 + (f >> 1) * 8;
                    int cc = c0 + (f & 1);
                    int p = atomicAdd(&g_cnt, 1);
                    if (p < MAXB) g_list[p] = make_int2(rr, cc);
                    if (bx != by) {
                        p = atomicAdd(&g_cnt, 1);
                        if (p < MAXB) g_list[p] = make_int2(cc, rr);
                    }
                }
            }
        }
}

// ===========================================================================
// Fixup: exact fp32 recompute of listed near-threshold scores
// ===========================================================================
__global__ void zero_cnt() { g_cnt = 0; }

__global__ __launch_bounds__(256) void fixup_band(
    const float* __restrict__ Z, float* __restrict__ S)
{
    const int wglobal = blockIdx.x * 8 + (threadIdx.x >> 5);
    const int lid = threadIdx.x & 31;
    const int nw = gridDim.x * 8;
    int cnt = g_cnt; if (cnt > MAXB) cnt = MAXB;
    for (int e = wglobal; e < cnt; e += nw) {
        int2 ij = g_list[e];
        const float* a = Z + (size_t)ij.x * KBIG;
        const float* b = Z + (size_t)ij.y * KBIG;
        float sum = 0.f;
        for (int k = lid; k < KBIG; k += 32) sum = fmaf(a[k], b[k], sum);
        #pragma unroll
        for (int o = 16; o; o >>= 1) sum += __shfl_xor_sync(0xffffffffu, sum, o);
        if (lid == 0) S[(size_t)ij.x * L_DIM + ij.y] = sum;
    }
}

// ===========================================================================
// SIMT double-buffered GEMM (GCN layers), now 2 CTAs/SM
// ===========================================================================
template <int BM, int BN, int TRANS_B, int RELU>
__global__ __launch_bounds__(256, 2) void gemm_db(
    const float* __restrict__ A, const float* __restrict__ B,
    float* __restrict__ C, int M, int N, int K)
{
    constexpr int TM = BM / 16;
    constexpr int TN = BN / 16;
    constexpr int NA = BM / 64;
    constexpr int NB = (16 * BN) / 1024;

    __shared__ float As[2][16][BM + 4];
    __shared__ float Bs[2][16][BN + 4];

    const int bm = blockIdx.y * BM;
    const int bn = blockIdx.x * BN;
    const int tid = threadIdx.x;
    const int tx  = tid & 15;
    const int ty  = tid >> 4;

    float acc[TM][TN];
    #pragma unroll
    for (int i = 0; i < TM; i++)
        #pragma unroll
        for (int j = 0; j < TN; j++) acc[i][j] = 0.f;

    float4 ra[NA], rb[NB];

    #define LD_A(k0)                                                          \
        _Pragma("unroll")                                                     \
        for (int t = 0; t < NA; t++) {                                        \
            int idx = tid + t * 256;                                          \
            int rr = idx >> 2, cc = (idx & 3) << 2;                           \
            ra[t] = *(const float4*)(A + (size_t)(bm + rr) * K + (k0) + cc);  \
        }
    #define LD_B(k0)                                                          \
        _Pragma("unroll")                                                     \
        for (int t = 0; t < NB; t++) {                                        \
            int idx = tid + t * 256;                                          \
            if (TRANS_B) {                                                    \
                int rr = idx >> 2, cc = (idx & 3) << 2;                       \
                rb[t] = *(const float4*)(B + (size_t)(bn + rr) * K + (k0) + cc); \
            } else {                                                          \
                int rr = idx / (BN / 4), cc = (idx % (BN / 4)) << 2;          \
                rb[t] = *(const float4*)(B + (size_t)((k0) + rr) * N + bn + cc); \
            }                                                                 \
        }
    #define ST_A(buf)                                                         \
        _Pragma("unroll")                                                     \
        for (int t = 0; t < NA; t++) {                                        \
            int idx = tid + t * 256;                                          \
            int rr = idx >> 2, cc = (idx & 3) << 2;                           \
            As[buf][cc + 0][rr] = ra[t].x; As[buf][cc + 1][rr] = ra[t].y;     \
            As[buf][cc + 2][rr] = ra[t].z; As[buf][cc + 3][rr] = ra[t].w;     \
        }
    #define ST_B(buf)                                                         \
        _Pragma("unroll")                                                     \
        for (int t = 0; t < NB; t++) {                                        \
            int idx = tid + t * 256;                                          \
            if (TRANS_B) {                                                    \
                int rr = idx >> 2, cc = (idx & 3) << 2;                       \
                Bs[buf][cc + 0][rr] = rb[t].x; Bs[buf][cc + 1][rr] = rb[t].y; \
                Bs[buf][cc + 2][rr] = rb[t].z; Bs[buf][cc + 3][rr] = rb[t].w; \
            } else {                                                          \
                int rr = idx / (BN / 4), cc = (idx % (BN / 4)) << 2;          \
                *(float4*)&Bs[buf][rr][cc] = rb[t];                           \
            }                                                                 \
        }

    const int nk = K >> 4;
    LD_A(0); LD_B(0);
    ST_A(0); ST_B(0);
    __syncthreads();

    int cur = 0;
    for (int kt = 0; kt < nk; kt++) {
        if (kt + 1 < nk) { int k0 = (kt + 1) << 4; LD_A(k0); LD_B(k0); }
        #pragma unroll
        for (int kk = 0; kk < 16; kk++) {
            float a[TM], b[TN];
            #pragma unroll
            for (int i = 0; i < TM; i += 4)
                *(float4*)(a + i) = *(const float4*)&As[cur][kk][ty * TM + i];
            #pragma unroll
            for (int j = 0; j < TN; j += 4)
                *(float4*)(b + j) = *(const float4*)&Bs[cur][kk][tx * TN + j];
            #pragma unroll
            for (int i = 0; i < TM; i++)
                #pragma unroll
                for (int j = 0; j < TN; j++)
                    acc[i][j] = fmaf(a[i], b[j], acc[i][j]);
        }
        if (kt + 1 < nk) { ST_A(cur ^ 1); ST_B(cur ^ 1); }
        __syncthreads();
        cur ^= 1;
    }

    #pragma unroll
    for (int i = 0; i < TM; i++) {
        float* crow = C + (size_t)(bm + ty * TM + i) * N + bn + tx * TN;
        #pragma unroll
        for (int j = 0; j < TN; j += 4) {
            float4 v;
            v.x = acc[i][j + 0]; v.y = acc[i][j + 1];
            v.z = acc[i][j + 2]; v.w = acc[i][j + 3];
            if (RELU) {
                v.x = fmaxf(v.x, 0.f); v.y = fmaxf(v.y, 0.f);
                v.z = fmaxf(v.z, 0.f); v.w = fmaxf(v.w, 0.f);
            }
            *(float4*)(crow + j) = v;
        }
    }
    #undef LD_A
    #undef LD_B
    #undef ST_A
    #undef ST_B
}

// ===========================================================================
// Masked softmax
// ===========================================================================
__global__ __launch_bounds__(256) void masked_softmax(float* __restrict__ S)
{
    __shared__ float red[8];
    const int r   = blockIdx.x;
    const int tid = threadIdx.x;
    float* row = S + (size_t)r * L_DIM;

    float m = -1e30f;
    for (int c = tid; c < L_DIM; c += 256) {
        float s = row[c];
        if (s >= 0.1f) m = fmaxf(m, s);
    }
    #pragma unroll
    for (int o = 16; o; o >>= 1) m = fmaxf(m, __shfl_xor_sync(0xffffffffu, m, o));
    if ((tid & 31) == 0) red[tid >> 5] = m;
    __syncthreads();
    float M = fmaxf(fmaxf(fmaxf(red[0], red[1]), fmaxf(red[2], red[3])),
                    fmaxf(fmaxf(red[4], red[5]), fmaxf(red[6], red[7])));
    __syncthreads();

    float sum = 0.f;
    for (int c = tid; c < L_DIM; c += 256) {
        float s = row[c];
        float e = (s >= 0.1f) ? expf(s - M) : 0.f;
        row[c] = e;
        sum += e;
    }
    #pragma unroll
    for (int o = 16; o; o >>= 1) sum += __shfl_xor_sync(0xffffffffu, sum, o);
    if ((tid & 31) == 0) red[tid >> 5] = sum;
    __syncthreads();
    float T = red[0] + red[1] + red[2] + red[3] +
              red[4] + red[5] + red[6] + red[7];
    float inv = 1.f / T;
    for (int c = tid; c < L_DIM; c += 256) row[c] *= inv;
}

// ===========================================================================
// Launch
// ===========================================================================
extern "C" void kernel_launch(void* const* d_in, const int* in_sizes, int n_in,
                              void* d_out, int out_size)
{
    const float* Lemb = (const float*)d_in[0];
    const float* Xpt  = (const float*)d_in[1];
    const float* Wpt  = (const float*)d_in[2];
    const float* W0   = (const float*)d_in[3];
    const float* W1   = (const float*)d_in[4];
    float* out = (float*)d_out;

    float *Z, *S, *T0, *X1, *T1;
    __nv_bfloat16 *Zhi, *Zlo;
    cudaGetSymbolAddress((void**)&Z,   g_Z);
    cudaGetSymbolAddress((void**)&Zhi, g_Zhi);
    cudaGetSymbolAddress((void**)&Zlo, g_Zlo);
    cudaGetSymbolAddress((void**)&S,   g_S);
    cudaGetSymbolAddress((void**)&T0,  g_T0);
    cudaGetSymbolAddress((void**)&X1,  g_X1);
    cudaGetSymbolAddress((void**)&T1,  g_T1);

    cudaFuncSetAttribute(zzt_mma, cudaFuncAttributeMaxDynamicSharedMemorySize,
                         ZZT_SMEM);

    // 0) reset band counter
    zero_cnt<<<1, 1>>>();

    // 1) Z + bf16 split
    compute_z<<<L_DIM, 256>>>(Xpt, Wpt, Z, Zhi, Zlo);

    // 2) scores = Z Z^T via mma.sync (3-pass bf16 split), symmetric,
    //    band scan fused into epilogue
    zzt_mma<<<dim3(16, 16), 256, ZZT_SMEM>>>(Zhi, Zlo, S);

    // 3) exact fp32 fixup of near-threshold entries
    fixup_band<<<512, 256>>>(Z, S);

    // 4) adj = softmax(threshold(scores))
    masked_softmax<<<L_DIM, 256>>>(S);

    // 5-8) GCN layers (SIMT fp32)
    gemm_db<128, 64, 0, 0><<<dim3(E_DIM / 64, L_DIM / 128), 256>>>(
        Lemb, W0, T0, L_DIM, E_DIM, E_DIM);
    gemm_db<128, 64, 0, 1><<<dim3(E_DIM / 64, L_DIM / 128), 256>>>(
        S, T0, X1, L_DIM, E_DIM, L_DIM);
    gemm_db<128, 64, 0, 0><<<dim3(E_DIM / 64, L_DIM / 128), 256>>>(
        X1, W1, T1, L_DIM, E_DIM, E_DIM);
    gemm_db<128, 64, 0, 1><<<dim3(E_DIM / 64, L_DIM / 128), 256>>>(
        S, T1, out, L_DIM, E_DIM, L_DIM);
}

// round 6
// speedup vs baseline: 2.1043x; 1.3268x over previous
#include <cuda_runtime.h>
#include <cuda_bf16.h>
#include <math.h>
#include <stdint.h>

// Problem constants
#define L_DIM   2048
#define E_DIM   512
#define EPT_DIM 300
#define H_DIM   16
#define KBIG    (H_DIM * EPT_DIM)   // 4800

// Scratch (allocation-free rule: __device__ globals)
__device__ float          g_Z  [L_DIM * KBIG];   // fp32 Z (exact fixup)
__device__ __nv_bfloat16  g_Zhi[L_DIM * KBIG];   // zzt inputs; reused as adj_hi
__device__ __nv_bfloat16  g_Zlo[L_DIM * KBIG];   // zzt inputs; reused as adj_lo
__device__ float g_S [L_DIM * L_DIM];            // scores (pre-softmax only)
__device__ float g_T0[L_DIM * E_DIM];            // reused as T0t_hi / T1t_hi (bf16)
__device__ float g_T1[L_DIM * E_DIM];            // reused as T0t_lo / T1t_lo (bf16)
__device__ float g_X1[L_DIM * E_DIM];            // X1 fp32

#define MAXB (1 << 18)
__device__ int  g_cnt;
__device__ int2 g_list[MAXB];

// ===========================================================================
// Helpers
// ===========================================================================
__device__ __forceinline__ uint32_t smem_u32(const void* p) {
    uint32_t a;
    asm("{ .reg .u64 t; cvta.to.shared.u64 t, %1; cvt.u32.u64 %0, t; }"
        : "=r"(a) : "l"(p));
    return a;
}
__device__ __forceinline__ void ldsm_x4(uint32_t* r, uint32_t addr) {
    asm volatile("ldmatrix.sync.aligned.m8n8.x4.shared.b16 {%0,%1,%2,%3}, [%4];"
                 : "=r"(r[0]), "=r"(r[1]), "=r"(r[2]), "=r"(r[3]) : "r"(addr));
}
__device__ __forceinline__ void mma_bf16(float* d, const uint32_t* a,
                                         const uint32_t* b) {
    asm volatile("mma.sync.aligned.m16n8k16.row.col.f32.bf16.bf16.f32 "
                 "{%0,%1,%2,%3}, {%4,%5,%6,%7}, {%8,%9}, {%0,%1,%2,%3};"
                 : "+f"(d[0]), "+f"(d[1]), "+f"(d[2]), "+f"(d[3])
                 : "r"(a[0]), "r"(a[1]), "r"(a[2]), "r"(a[3]),
                   "r"(b[0]), "r"(b[1]));
}
#define CP_ASYNC16(dst, src) \
    asm volatile("cp.async.cg.shared.global [%0], [%1], 16;" \
                 :: "r"(dst), "l"(src))
#define CP_COMMIT()  asm volatile("cp.async.commit_group;" ::: "memory")
#define CP_WAIT(N)   asm volatile("cp.async.wait_group " #N ";" ::: "memory")

// ===========================================================================
// Kernel 1: Z + bf16 hi/lo split. Warp per (l, h): block l, 16 warps.
// ===========================================================================
__global__ __launch_bounds__(512) void compute_z(
    const float* __restrict__ xpt, const float* __restrict__ Wpt,
    float* __restrict__ Z, __nv_bfloat16* __restrict__ Zhi,
    __nv_bfloat16* __restrict__ Zlo)
{
    const int l    = blockIdx.x;
    const int h    = threadIdx.x >> 5;
    const int lane = threadIdx.x & 31;

    const float* xrow = xpt + (size_t)l * EPT_DIM;
    const float* wrow = Wpt + h * EPT_DIM;

    float v[10];
    float ss = 0.f;
    #pragma unroll
    for (int i = 0; i < 10; i++) {
        int e = lane + i * 32;
        float vv = 0.f;
        if (e < EPT_DIM) {
            float w = wrow[e];
            vv = xrow[e] * w * w;
        }
        v[i] = vv;
        ss += vv * vv;
    }
    #pragma unroll
    for (int o = 16; o; o >>= 1) ss += __shfl_xor_sync(0xffffffffu, ss, o);
    float inv = 0.25f / fmaxf(sqrtf(ss), 1e-12f);   // 1/sqrt(H)=0.25 folded

    size_t base = (size_t)l * KBIG + h * EPT_DIM;
    #pragma unroll
    for (int i = 0; i < 10; i++) {
        int e = lane + i * 32;
        if (e < EPT_DIM) {
            float val = v[i] * inv;
            __nv_bfloat16 hb = __float2bfloat16(val);
            Z[base + e]   = val;
            Zhi[base + e] = hb;
            Zlo[base + e] = __float2bfloat16(val - __bfloat162float(hb));
        }
    }
}

// ===========================================================================
// Kernel 2: ZZ^T via mma.sync, 3-stage cp.async, hoisted addressing, symmetric.
// 128x128 CTA tile, BK=64, 8 warps (2x4), warp tile 64x32, 3-pass hi/lo.
// ===========================================================================
#define TILE_B   16384
#define STAGE_B  (4 * TILE_B)
#define ZZT_SMEM (3 * STAGE_B + 128)

__global__ void __launch_bounds__(256, 1) zzt_mma(
    const __nv_bfloat16* __restrict__ Zhi,
    const __nv_bfloat16* __restrict__ Zlo,
    float* __restrict__ S)
{
    const int bx = blockIdx.x, by = blockIdx.y;
    if (bx < by) return;
    extern __shared__ char smem_raw[];
    const uint32_t sb = (smem_u32(smem_raw) + 127u) & ~127u;

    const int tid  = threadIdx.x;
    const int wid  = tid >> 5, lane = tid & 31;
    const int bm = by << 7, bn = bx << 7;
    const int wm = wid >> 2, wn = wid & 3;

    float acc[4][4][4];
    #pragma unroll
    for (int mt = 0; mt < 4; mt++)
        #pragma unroll
        for (int nt = 0; nt < 4; nt++)
            #pragma unroll
            for (int f = 0; f < 4; f++) acc[mt][nt][f] = 0.f;

    // hoisted ldmatrix offsets
    uint32_t offA[4][4], offBp[2][4];
    #pragma unroll
    for (int mt = 0; mt < 4; mt++) {
        int r  = wm * 64 + mt * 16 + (lane & 15);
        int r7 = r & 7;
        #pragma unroll
        for (int ks = 0; ks < 4; ks++) {
            int ch = ks * 2 + (lane >> 4);
            offA[mt][ks] = r * 128 + ((ch ^ r7) << 4);
        }
    }
    #pragma unroll
    for (int p = 0; p < 2; p++) {
        int ntl = p * 2 + ((lane >> 4) & 1);
        int r   = wn * 32 + ntl * 8 + (lane & 7);
        int r7  = r & 7;
        #pragma unroll
        for (int ks = 0; ks < 4; ks++) {
            int ch = ks * 2 + ((lane >> 3) & 1);
            offBp[p][ks] = r * 128 + ((ch ^ r7) << 4);
        }
    }

    // hoisted cp.async offsets
    uint32_t dstoff[4];
    int      srcA[4], srcB[4];
    #pragma unroll
    for (int t = 0; t < 4; t++) {
        int idx = tid + t * 256;
        int r = idx >> 3, ch = idx & 7;
        dstoff[t] = (uint32_t)(r * 128 + ((ch ^ (r & 7)) << 4));
        srcA[t] = (bm + r) * KBIG + ch * 8;
        srcB[t] = (bn + r) * KBIG + ch * 8;
    }

    auto cp_stage = [&](int s, int kt) {
        const int k0 = kt << 6;
        const uint32_t base = sb + (uint32_t)s * STAGE_B;
        #pragma unroll
        for (int t = 0; t < 4; t++) {
            CP_ASYNC16(base + dstoff[t],              Zhi + srcA[t] + k0);
            CP_ASYNC16(base + TILE_B + dstoff[t],     Zlo + srcA[t] + k0);
            CP_ASYNC16(base + 2 * TILE_B + dstoff[t], Zhi + srcB[t] + k0);
            CP_ASYNC16(base + 3 * TILE_B + dstoff[t], Zlo + srcB[t] + k0);
        }
        CP_COMMIT();
    };

    auto compute = [&](int s) {
        const uint32_t pa = sb + (uint32_t)s * STAGE_B;
        #pragma unroll
        for (int ks = 0; ks < 4; ks++) {
            uint32_t ahi[4][4], alo[4][4];
            #pragma unroll
            for (int mt = 0; mt < 4; mt++) {
                ldsm_x4(ahi[mt], pa + offA[mt][ks]);
                ldsm_x4(alo[mt], pa + TILE_B + offA[mt][ks]);
            }
            #pragma unroll
            for (int p = 0; p < 2; p++) {
                uint32_t bh[4], bl[4];
                ldsm_x4(bh, pa + 2 * TILE_B + offBp[p][ks]);
                ldsm_x4(bl, pa + 3 * TILE_B + offBp[p][ks]);
                #pragma unroll
                for (int half = 0; half < 2; half++) {
                    int nt = p * 2 + half;
                    #pragma unroll
                    for (int mt = 0; mt < 4; mt++) {
                        mma_bf16(acc[mt][nt], ahi[mt], bh + 2 * half);
                        mma_bf16(acc[mt][nt], ahi[mt], bl + 2 * half);
                        mma_bf16(acc[mt][nt], alo[mt], bh + 2 * half);
                    }
                }
            }
        }
    };

    const int NKT = KBIG / 64;   // 75
    cp_stage(0, 0);
    cp_stage(1, 1);
    int sc = 0, s2 = 2;
    for (int kt = 0; kt < NKT; kt++) {
        if (kt + 1 < NKT) { CP_WAIT(1); } else { CP_WAIT(0); }
        __syncthreads();
        if (kt + 2 < NKT) cp_stage(s2, kt + 2);
        compute(sc);
        if (++sc == 3) sc = 0;
        if (++s2 == 3) s2 = 0;
    }

    // epilogue: stores + fused near-threshold band scan
    #pragma unroll
    for (int mt = 0; mt < 4; mt++)
        #pragma unroll
        for (int nt = 0; nt < 4; nt++) {
            const int r0 = bm + wm * 64 + mt * 16 + (lane >> 2);
            const int c0 = bn + wn * 32 + nt * 8 + (lane & 3) * 2;
            const float* d = acc[mt][nt];
            *(float2*)(S + (size_t)r0 * L_DIM + c0)       = make_float2(d[0], d[1]);
            *(float2*)(S + (size_t)(r0 + 8) * L_DIM + c0) = make_float2(d[2], d[3]);
            if (bx != by) {
                S[(size_t)c0 * L_DIM + r0]           = d[0];
                S[(size_t)(c0 + 1) * L_DIM + r0]     = d[1];
                S[(size_t)c0 * L_DIM + r0 + 8]       = d[2];
                S[(size_t)(c0 + 1) * L_DIM + r0 + 8] = d[3];
            }
            #pragma unroll
            for (int f = 0; f < 4; f++) {
                if (fabsf(d[f] - 0.1f) < 3e-4f) {
                    int rr = r0 + (f >> 1) * 8;
                    int cc = c0 + (f & 1);
                    int p = atomicAdd(&g_cnt, 1);
                    if (p < MAXB) g_list[p] = make_int2(rr, cc);
                    if (bx != by) {
                        p = atomicAdd(&g_cnt, 1);
                        if (p < MAXB) g_list[p] = make_int2(cc, rr);
                    }
                }
            }
        }
}

// ===========================================================================
// Fixup: exact fp32 recompute (float4 loads)
// ===========================================================================
__global__ void zero_cnt() { g_cnt = 0; }

__global__ __launch_bounds__(256) void fixup_band(
    const float* __restrict__ Z, float* __restrict__ S)
{
    const int wglobal = blockIdx.x * 8 + (threadIdx.x >> 5);
    const int lid = threadIdx.x & 31;
    const int nw = gridDim.x * 8;
    int cnt = g_cnt; if (cnt > MAXB) cnt = MAXB;
    for (int e = wglobal; e < cnt; e += nw) {
        int2 ij = g_list[e];
        const float4* a = (const float4*)(Z + (size_t)ij.x * KBIG);
        const float4* b = (const float4*)(Z + (size_t)ij.y * KBIG);
        float sum = 0.f;
        for (int k = lid; k < KBIG / 4; k += 32) {
            float4 av = a[k], bv = b[k];
            sum = fmaf(av.x, bv.x, sum);
            sum = fmaf(av.y, bv.y, sum);
            sum = fmaf(av.z, bv.z, sum);
            sum = fmaf(av.w, bv.w, sum);
        }
        #pragma unroll
        for (int o = 16; o; o >>= 1) sum += __shfl_xor_sync(0xffffffffu, sum, o);
        if (lid == 0) S[(size_t)ij.x * L_DIM + ij.y] = sum;
    }
}

// ===========================================================================
// Masked softmax -> adj bf16 hi/lo splits (adj fp32 not materialized)
// ===========================================================================
__global__ __launch_bounds__(256) void masked_softmax(
    const float* __restrict__ S,
    __nv_bfloat16* __restrict__ Phi, __nv_bfloat16* __restrict__ Plo)
{
    __shared__ float red[8];
    const int r   = blockIdx.x;
    const int tid = threadIdx.x;
    const float* row = S + (size_t)r * L_DIM;

    float m = -1e30f;
    for (int c = tid; c < L_DIM; c += 256) {
        float s = row[c];
        if (s >= 0.1f) m = fmaxf(m, s);
    }
    #pragma unroll
    for (int o = 16; o; o >>= 1) m = fmaxf(m, __shfl_xor_sync(0xffffffffu, m, o));
    if ((tid & 31) == 0) red[tid >> 5] = m;
    __syncthreads();
    float M = fmaxf(fmaxf(fmaxf(red[0], red[1]), fmaxf(red[2], red[3])),
                    fmaxf(fmaxf(red[4], red[5]), fmaxf(red[6], red[7])));
    __syncthreads();

    float sum = 0.f;
    for (int c = tid; c < L_DIM; c += 256) {
        float s = row[c];
        float e = (s >= 0.1f) ? expf(s - M) : 0.f;
        sum += e;
    }
    #pragma unroll
    for (int o = 16; o; o >>= 1) sum += __shfl_xor_sync(0xffffffffu, sum, o);
    if ((tid & 31) == 0) red[tid >> 5] = sum;
    __syncthreads();
    float T = red[0] + red[1] + red[2] + red[3] +
              red[4] + red[5] + red[6] + red[7];
    float inv = 1.f / T;

    for (int c = tid; c < L_DIM; c += 256) {
        float s = row[c];
        float v = (s >= 0.1f) ? expf(s - M) * inv : 0.f;
        __nv_bfloat16 hb = __float2bfloat16(v);
        Phi[(size_t)r * L_DIM + c] = hb;
        Plo[(size_t)r * L_DIM + c] = __float2bfloat16(v - __bfloat162float(hb));
    }
}

// ===========================================================================
// gcn_mma: C = relu(A @ B^T), A = adj hi/lo [2048 x 2048], B = Tt hi/lo
// [512 rows x 2048 K], C fp32 [2048 x 512]. 128x64 tile, 8 warps (2x4),
// warp tile 64x16, 3-pass hi/lo, 3-stage cp.async.
// ===========================================================================
#define GA_B 16384                 // A part: 128 rows x 128B
#define GB_B 8192                  // B part: 64 rows x 128B
#define GSTAGE_B (2 * GA_B + 2 * GB_B)   // 48 KB
#define GCN_SMEM (3 * GSTAGE_B + 128)

__global__ void __launch_bounds__(256, 1) gcn_mma(
    const __nv_bfloat16* __restrict__ Ahi, const __nv_bfloat16* __restrict__ Alo,
    const __nv_bfloat16* __restrict__ Bhi, const __nv_bfloat16* __restrict__ Blo,
    float* __restrict__ C)
{
    const int K = L_DIM;           // 2048
    extern __shared__ char smem_raw[];
    const uint32_t sb = (smem_u32(smem_raw) + 127u) & ~127u;

    const int tid  = threadIdx.x;
    const int wid  = tid >> 5, lane = tid & 31;
    const int bm = blockIdx.y << 7;        // M tile (16)
    const int bn = blockIdx.x << 6;        // N tile (8)
    const int wm = wid >> 2, wn = wid & 3; // warp 64x16

    float acc[4][2][4];
    #pragma unroll
    for (int mt = 0; mt < 4; mt++)
        #pragma unroll
        for (int nt = 0; nt < 2; nt++)
            #pragma unroll
            for (int f = 0; f < 4; f++) acc[mt][nt][f] = 0.f;

    uint32_t offA[4][4], offB[4];
    #pragma unroll
    for (int mt = 0; mt < 4; mt++) {
        int r  = wm * 64 + mt * 16 + (lane & 15);
        int r7 = r & 7;
        #pragma unroll
        for (int ks = 0; ks < 4; ks++) {
            int ch = ks * 2 + (lane >> 4);
            offA[mt][ks] = r * 128 + ((ch ^ r7) << 4);
        }
    }
    {
        int ntl = (lane >> 4) & 1;
        int r   = wn * 16 + ntl * 8 + (lane & 7);
        int r7  = r & 7;
        #pragma unroll
        for (int ks = 0; ks < 4; ks++) {
            int ch = ks * 2 + ((lane >> 3) & 1);
            offB[ks] = r * 128 + ((ch ^ r7) << 4);
        }
    }

    uint32_t dstA[4]; int srcA[4];
    #pragma unroll
    for (int t = 0; t < 4; t++) {
        int idx = tid + t * 256;
        int r = idx >> 3, ch = idx & 7;
        dstA[t] = (uint32_t)(r * 128 + ((ch ^ (r & 7)) << 4));
        srcA[t] = (bm + r) * K + ch * 8;
    }
    uint32_t dstB[2]; int srcB[2];
    #pragma unroll
    for (int t = 0; t < 2; t++) {
        int idx = tid + t * 256;
        int r = idx >> 3, ch = idx & 7;
        dstB[t] = (uint32_t)(r * 128 + ((ch ^ (r & 7)) << 4));
        srcB[t] = (bn + r) * K + ch * 8;
    }

    auto cp_stage = [&](int s, int kt) {
        const int k0 = kt << 6;
        const uint32_t base = sb + (uint32_t)s * GSTAGE_B;
        #pragma unroll
        for (int t = 0; t < 4; t++) {
            CP_ASYNC16(base + dstA[t],        Ahi + srcA[t] + k0);
            CP_ASYNC16(base + GA_B + dstA[t], Alo + srcA[t] + k0);
        }
        #pragma unroll
        for (int t = 0; t < 2; t++) {
            CP_ASYNC16(base + 2 * GA_B + dstB[t],        Bhi + srcB[t] + k0);
            CP_ASYNC16(base + 2 * GA_B + GB_B + dstB[t], Blo + srcB[t] + k0);
        }
        CP_COMMIT();
    };

    auto compute = [&](int s) {
        const uint32_t pa = sb + (uint32_t)s * GSTAGE_B;
        #pragma unroll
        for (int ks = 0; ks < 4; ks++) {
            uint32_t ahi[4][4], alo[4][4], bh[4], bl[4];
            #pragma unroll
            for (int mt = 0; mt < 4; mt++) {
                ldsm_x4(ahi[mt], pa + offA[mt][ks]);
                ldsm_x4(alo[mt], pa + GA_B + offA[mt][ks]);
            }
            ldsm_x4(bh, pa + 2 * GA_B + offB[ks]);
            ldsm_x4(bl, pa + 2 * GA_B + GB_B + offB[ks]);
            #pragma unroll
            for (int nt = 0; nt < 2; nt++)
                #pragma unroll
                for (int mt = 0; mt < 4; mt++) {
                    mma_bf16(acc[mt][nt], ahi[mt], bh + 2 * nt);
                    mma_bf16(acc[mt][nt], ahi[mt], bl + 2 * nt);
                    mma_bf16(acc[mt][nt], alo[mt], bh + 2 * nt);
                }
        }
    };

    const int NKT = K / 64;   // 32
    cp_stage(0, 0);
    cp_stage(1, 1);
    int sc = 0, s2 = 2;
    for (int kt = 0; kt < NKT; kt++) {
        if (kt + 1 < NKT) { CP_WAIT(1); } else { CP_WAIT(0); }
        __syncthreads();
        if (kt + 2 < NKT) cp_stage(s2, kt + 2);
        compute(sc);
        if (++sc == 3) sc = 0;
        if (++s2 == 3) s2 = 0;
    }

    #pragma unroll
    for (int mt = 0; mt < 4; mt++)
        #pragma unroll
        for (int nt = 0; nt < 2; nt++) {
            const int r0 = bm + wm * 64 + mt * 16 + (lane >> 2);
            const int c0 = bn + wn * 16 + nt * 8 + (lane & 3) * 2;
            const float* d = acc[mt][nt];
            *(float2*)(C + (size_t)r0 * E_DIM + c0) =
                make_float2(fmaxf(d[0], 0.f), fmaxf(d[1], 0.f));
            *(float2*)(C + (size_t)(r0 + 8) * E_DIM + c0) =
                make_float2(fmaxf(d[2], 0.f), fmaxf(d[3], 0.f));
        }
}

// ===========================================================================
// SIMT double-buffered GEMM: C = A @ B, epilogue writes TRANSPOSED bf16 hi/lo
// (Ct[n][m], ld = M). Used for Lemb@W0 -> T0t and X1@W1 -> T1t.
// ===========================================================================
__global__ __launch_bounds__(256, 2) void gemm_split_t(
    const float* __restrict__ A, const float* __restrict__ B,
    __nv_bfloat16* __restrict__ Chi, __nv_bfloat16* __restrict__ Clo,
    int M, int N, int K)
{
    constexpr int BM = 128, BN = 64;
    constexpr int TM = 8, TN = 4;
    constexpr int NA = 2, NB = 1;

    __shared__ float As[2][16][BM + 4];
    __shared__ float Bs[2][16][BN + 4];

    const int bm = blockIdx.y * BM;
    const int bn = blockIdx.x * BN;
    const int tid = threadIdx.x;
    const int tx  = tid & 15;
    const int ty  = tid >> 4;

    float acc[TM][TN];
    #pragma unroll
    for (int i = 0; i < TM; i++)
        #pragma unroll
        for (int j = 0; j < TN; j++) acc[i][j] = 0.f;

    float4 ra[NA], rb[NB];

    #define LD_A(k0)                                                          \
        _Pragma("unroll")                                                     \
        for (int t = 0; t < NA; t++) {                                        \
            int idx = tid + t * 256;                                          \
            int rr = idx >> 2, cc = (idx & 3) << 2;                           \
            ra[t] = *(const float4*)(A + (size_t)(bm + rr) * K + (k0) + cc);  \
        }
    #define LD_B(k0)                                                          \
        _Pragma("unroll")                                                     \
        for (int t = 0; t < NB; t++) {                                        \
            int idx = tid + t * 256;                                          \
            int rr = idx / (BN / 4), cc = (idx % (BN / 4)) << 2;              \
            rb[t] = *(const float4*)(B + (size_t)((k0) + rr) * N + bn + cc);  \
        }
    #define ST_A(buf)                                                         \
        _Pragma("unroll")                                                     \
        for (int t = 0; t < NA; t++) {                                        \
            int idx = tid + t * 256;                                          \
            int rr = idx >> 2, cc = (idx & 3) << 2;                           \
            As[buf][cc + 0][rr] = ra[t].x; As[buf][cc + 1][rr] = ra[t].y;     \
            As[buf][cc + 2][rr] = ra[t].z; As[buf][cc + 3][rr] = ra[t].w;     \
        }
    #define ST_B(buf)                                                         \
        _Pragma("unroll")                                                     \
        for (int t = 0; t < NB; t++) {                                        \
            int idx = tid + t * 256;                                          \
            int rr = idx / (BN / 4), cc = (idx % (BN / 4)) << 2;              \
            *(float4*)&Bs[buf][rr][cc] = rb[t];                               \
        }

    const int nk = K >> 4;
    LD_A(0); LD_B(0);
    ST_A(0); ST_B(0);
    __syncthreads();

    int cur = 0;
    for (int kt = 0; kt < nk; kt++) {
        if (kt + 1 < nk) { int k0 = (kt + 1) << 4; LD_A(k0); LD_B(k0); }
        #pragma unroll
        for (int kk = 0; kk < 16; kk++) {
            float a[TM], b[TN];
            #pragma unroll
            for (int i = 0; i < TM; i += 4)
                *(float4*)(a + i) = *(const float4*)&As[cur][kk][ty * TM + i];
            *(float4*)(b) = *(const float4*)&Bs[cur][kk][tx * TN];
            #pragma unroll
            for (int i = 0; i < TM; i++)
                #pragma unroll
                for (int j = 0; j < TN; j++)
                    acc[i][j] = fmaf(a[i], b[j], acc[i][j]);
        }
        if (kt + 1 < nk) { ST_A(cur ^ 1); ST_B(cur ^ 1); }
        __syncthreads();
        cur ^= 1;
    }

    // transposed split epilogue: Ct[n][m]
    #pragma unroll
    for (int j = 0; j < TN; j++) {
        size_t rowb = (size_t)(bn + tx * TN + j) * M + bm + ty * TM;
        #pragma unroll
        for (int i = 0; i < TM; i++) {
            float v = acc[i][j];
            __nv_bfloat16 hb = __float2bfloat16(v);
            Chi[rowb + i] = hb;
            Clo[rowb + i] = __float2bfloat16(v - __bfloat162float(hb));
        }
    }
    #undef LD_A
    #undef LD_B
    #undef ST_A
    #undef ST_B
}

// ===========================================================================
// Launch
// ===========================================================================
extern "C" void kernel_launch(void* const* d_in, const int* in_sizes, int n_in,
                              void* d_out, int out_size)
{
    const float* Lemb = (const float*)d_in[0];
    const float* Xpt  = (const float*)d_in[1];
    const float* Wpt  = (const float*)d_in[2];
    const float* W0   = (const float*)d_in[3];
    const float* W1   = (const float*)d_in[4];
    float* out = (float*)d_out;

    float *Z, *S, *T0, *X1, *T1;
    __nv_bfloat16 *Zhi, *Zlo;
    cudaGetSymbolAddress((void**)&Z,   g_Z);
    cudaGetSymbolAddress((void**)&Zhi, g_Zhi);
    cudaGetSymbolAddress((void**)&Zlo, g_Zlo);
    cudaGetSymbolAddress((void**)&S,   g_S);
    cudaGetSymbolAddress((void**)&T0,  g_T0);
    cudaGetSymbolAddress((void**)&X1,  g_X1);
    cudaGetSymbolAddress((void**)&T1,  g_T1);

    // buffer reuse
    __nv_bfloat16* Phi = Zhi;                       // adj hi (after zzt)
    __nv_bfloat16* Plo = Zlo;                       // adj lo
    __nv_bfloat16* Tt_hi = (__nv_bfloat16*)T0;      // T0t/T1t hi [512 x 2048]
    __nv_bfloat16* Tt_lo = (__nv_bfloat16*)T1;      // T0t/T1t lo

    cudaFuncSetAttribute(zzt_mma, cudaFuncAttributeMaxDynamicSharedMemorySize,
                         ZZT_SMEM);
    cudaFuncSetAttribute(gcn_mma, cudaFuncAttributeMaxDynamicSharedMemorySize,
                         GCN_SMEM);

    zero_cnt<<<1, 1>>>();

    // 1) Z + bf16 split (warp per (l,h))
    compute_z<<<L_DIM, 512>>>(Xpt, Wpt, Z, Zhi, Zlo);

    // 2) scores = Z Z^T (mma.sync 3-pass), band scan fused
    zzt_mma<<<dim3(16, 16), 256, ZZT_SMEM>>>(Zhi, Zlo, S);

    // 3) exact fp32 fixup of near-threshold entries
    fixup_band<<<256, 256>>>(Z, S);

    // 4) adj = softmax(threshold(scores)) -> bf16 hi/lo splits
    masked_softmax<<<L_DIM, 256>>>(S, Phi, Plo);

    // 5) T0t = (Lemb @ W0)^T as bf16 hi/lo
    gemm_split_t<<<dim3(E_DIM / 64, L_DIM / 128), 256>>>(
        Lemb, W0, Tt_hi, Tt_lo, L_DIM, E_DIM, E_DIM);

    // 6) X1 = relu(adj @ T0)  (mma.sync 3-pass)
    gcn_mma<<<dim3(E_DIM / 64, L_DIM / 128), 256, GCN_SMEM>>>(
        Phi, Plo, Tt_hi, Tt_lo, X1);

    // 7) T1t = (X1 @ W1)^T as bf16 hi/lo (overwrites T0t)
    gemm_split_t<<<dim3(E_DIM / 64, L_DIM / 128), 256>>>(
        X1, W1, Tt_hi, Tt_lo, L_DIM, E_DIM, E_DIM);

    // 8) out = relu(adj @ T1)
    gcn_mma<<<dim3(E_DIM / 64, L_DIM / 128), 256, GCN_SMEM>>>(
        Phi, Plo, Tt_hi, Tt_lo, out);
}

// round 7
// speedup vs baseline: 2.8494x; 1.3541x over previous
#include <cuda_runtime.h>
#include <cuda_bf16.h>
#include <math.h>
#include <stdint.h>

// Problem constants
#define L_DIM   2048
#define E_DIM   512
#define EPT_DIM 300
#define H_DIM   16
#define KBIG    (H_DIM * EPT_DIM)   // 4800

// Scratch (allocation-free rule: __device__ globals)
__device__ float          g_Z  [L_DIM * KBIG];   // fp32 Z (exact fixup)
__device__ __nv_bfloat16  g_Zhi[L_DIM * KBIG];   // zzt input; reused as adj_hi
__device__ __nv_bfloat16  g_Zlo[L_DIM * KBIG];   // reused as adj_lo
__device__ float g_S [L_DIM * L_DIM];            // scores (pre-softmax)
__device__ float g_T0[L_DIM * E_DIM];            // reused as Tt_hi (bf16)
__device__ float g_T1[L_DIM * E_DIM];            // reused as Tt_lo (bf16)
__device__ float g_X1[L_DIM * E_DIM];            // X1 fp32

#define MAXB (1 << 18)
#define BANDW 2.5e-4f
__device__ int  g_cnt;
__device__ int2 g_list[MAXB];

// ===========================================================================
// Helpers
// ===========================================================================
__device__ __forceinline__ uint32_t smem_u32(const void* p) {
    uint32_t a;
    asm("{ .reg .u64 t; cvta.to.shared.u64 t, %1; cvt.u32.u64 %0, t; }"
        : "=r"(a) : "l"(p));
    return a;
}
__device__ __forceinline__ void ldsm_x4(uint32_t* r, uint32_t addr) {
    asm volatile("ldmatrix.sync.aligned.m8n8.x4.shared.b16 {%0,%1,%2,%3}, [%4];"
                 : "=r"(r[0]), "=r"(r[1]), "=r"(r[2]), "=r"(r[3]) : "r"(addr));
}
__device__ __forceinline__ void mma_bf16(float* d, const uint32_t* a,
                                         const uint32_t* b) {
    asm volatile("mma.sync.aligned.m16n8k16.row.col.f32.bf16.bf16.f32 "
                 "{%0,%1,%2,%3}, {%4,%5,%6,%7}, {%8,%9}, {%0,%1,%2,%3};"
                 : "+f"(d[0]), "+f"(d[1]), "+f"(d[2]), "+f"(d[3])
                 : "r"(a[0]), "r"(a[1]), "r"(a[2]), "r"(a[3]),
                   "r"(b[0]), "r"(b[1]));
}
#define CP_ASYNC16(dst, src) \
    asm volatile("cp.async.cg.shared.global [%0], [%1], 16;" \
                 :: "r"(dst), "l"(src))
#define CP_COMMIT()  asm volatile("cp.async.commit_group;" ::: "memory")
#define CP_WAIT(N)   asm volatile("cp.async.wait_group " #N ";" ::: "memory")

// ===========================================================================
// Kernel 1: Z (fp32) + Zhi (bf16). Warp per (l, h).
// ===========================================================================
__global__ __launch_bounds__(512) void compute_z(
    const float* __restrict__ xpt, const float* __restrict__ Wpt,
    float* __restrict__ Z, __nv_bfloat16* __restrict__ Zhi)
{
    const int l    = blockIdx.x;
    const int h    = threadIdx.x >> 5;
    const int lane = threadIdx.x & 31;

    const float* xrow = xpt + (size_t)l * EPT_DIM;
    const float* wrow = Wpt + h * EPT_DIM;

    float v[10];
    float ss = 0.f;
    #pragma unroll
    for (int i = 0; i < 10; i++) {
        int e = lane + i * 32;
        float vv = 0.f;
        if (e < EPT_DIM) {
            float w = wrow[e];
            vv = xrow[e] * w * w;
        }
        v[i] = vv;
        ss += vv * vv;
    }
    #pragma unroll
    for (int o = 16; o; o >>= 1) ss += __shfl_xor_sync(0xffffffffu, ss, o);
    float inv = 0.25f / fmaxf(sqrtf(ss), 1e-12f);

    size_t base = (size_t)l * KBIG + h * EPT_DIM;
    #pragma unroll
    for (int i = 0; i < 10; i++) {
        int e = lane + i * 32;
        if (e < EPT_DIM) {
            float val = v[i] * inv;
            Z[base + e]   = val;
            Zhi[base + e] = __float2bfloat16(val);
        }
    }
}

// ===========================================================================
// Kernel 2: ZZ^T single-pass bf16 via mma.sync; 3-stage cp.async; symmetric.
// 128x128 CTA tile, BK=64, 8 warps (2x4), warp tile 64x32.
// Band (±2.5e-4 around 0.1) recorded in epilogue; fixed up exactly later.
// ===========================================================================
#define TILE_B   16384
#define STAGE_B  (2 * TILE_B)
#define ZZT_SMEM (3 * STAGE_B + 128)

__global__ void __launch_bounds__(256, 1) zzt_mma(
    const __nv_bfloat16* __restrict__ Zhi, float* __restrict__ S)
{
    const int bx = blockIdx.x, by = blockIdx.y;
    if (bx < by) return;
    extern __shared__ char smem_raw[];
    const uint32_t sb = (smem_u32(smem_raw) + 127u) & ~127u;

    const int tid  = threadIdx.x;
    const int wid  = tid >> 5, lane = tid & 31;
    const int bm = by << 7, bn = bx << 7;
    const int wm = wid >> 2, wn = wid & 3;

    float acc[4][4][4];
    #pragma unroll
    for (int mt = 0; mt < 4; mt++)
        #pragma unroll
        for (int nt = 0; nt < 4; nt++)
            #pragma unroll
            for (int f = 0; f < 4; f++) acc[mt][nt][f] = 0.f;

    uint32_t offA[4][4], offBp[2][4];
    #pragma unroll
    for (int mt = 0; mt < 4; mt++) {
        int r  = wm * 64 + mt * 16 + (lane & 15);
        int r7 = r & 7;
        #pragma unroll
        for (int ks = 0; ks < 4; ks++) {
            int ch = ks * 2 + (lane >> 4);
            offA[mt][ks] = r * 128 + ((ch ^ r7) << 4);
        }
    }
    #pragma unroll
    for (int p = 0; p < 2; p++) {
        int ntl = p * 2 + ((lane >> 4) & 1);
        int r   = wn * 32 + ntl * 8 + (lane & 7);
        int r7  = r & 7;
        #pragma unroll
        for (int ks = 0; ks < 4; ks++) {
            int ch = ks * 2 + ((lane >> 3) & 1);
            offBp[p][ks] = r * 128 + ((ch ^ r7) << 4);
        }
    }

    uint32_t dstoff[4];
    int      srcA[4], srcB[4];
    #pragma unroll
    for (int t = 0; t < 4; t++) {
        int idx = tid + t * 256;
        int r = idx >> 3, ch = idx & 7;
        dstoff[t] = (uint32_t)(r * 128 + ((ch ^ (r & 7)) << 4));
        srcA[t] = (bm + r) * KBIG + ch * 8;
        srcB[t] = (bn + r) * KBIG + ch * 8;
    }

    auto cp_stage = [&](int s, int kt) {
        const int k0 = kt << 6;
        const uint32_t base = sb + (uint32_t)s * STAGE_B;
        #pragma unroll
        for (int t = 0; t < 4; t++) {
            CP_ASYNC16(base + dstoff[t],          Zhi + srcA[t] + k0);
            CP_ASYNC16(base + TILE_B + dstoff[t], Zhi + srcB[t] + k0);
        }
        CP_COMMIT();
    };

    auto compute = [&](int s) {
        const uint32_t pa = sb + (uint32_t)s * STAGE_B;
        #pragma unroll
        for (int ks = 0; ks < 4; ks++) {
            uint32_t ah[4][4];
            #pragma unroll
            for (int mt = 0; mt < 4; mt++)
                ldsm_x4(ah[mt], pa + offA[mt][ks]);
            #pragma unroll
            for (int p = 0; p < 2; p++) {
                uint32_t bh[4];
                ldsm_x4(bh, pa + TILE_B + offBp[p][ks]);
                #pragma unroll
                for (int half = 0; half < 2; half++) {
                    int nt = p * 2 + half;
                    #pragma unroll
                    for (int mt = 0; mt < 4; mt++)
                        mma_bf16(acc[mt][nt], ah[mt], bh + 2 * half);
                }
            }
        }
    };

    const int NKT = KBIG / 64;   // 75
    cp_stage(0, 0);
    cp_stage(1, 1);
    int sc = 0, s2 = 2;
    for (int kt = 0; kt < NKT; kt++) {
        if (kt + 1 < NKT) { CP_WAIT(1); } else { CP_WAIT(0); }
        __syncthreads();
        if (kt + 2 < NKT) cp_stage(s2, kt + 2);
        compute(sc);
        if (++sc == 3) sc = 0;
        if (++s2 == 3) s2 = 0;
    }

    // epilogue: stores + fused near-threshold band scan
    #pragma unroll
    for (int mt = 0; mt < 4; mt++)
        #pragma unroll
        for (int nt = 0; nt < 4; nt++) {
            const int r0 = bm + wm * 64 + mt * 16 + (lane >> 2);
            const int c0 = bn + wn * 32 + nt * 8 + (lane & 3) * 2;
            const float* d = acc[mt][nt];
            *(float2*)(S + (size_t)r0 * L_DIM + c0)       = make_float2(d[0], d[1]);
            *(float2*)(S + (size_t)(r0 + 8) * L_DIM + c0) = make_float2(d[2], d[3]);
            if (bx != by) {
                S[(size_t)c0 * L_DIM + r0]           = d[0];
                S[(size_t)(c0 + 1) * L_DIM + r0]     = d[1];
                S[(size_t)c0 * L_DIM + r0 + 8]       = d[2];
                S[(size_t)(c0 + 1) * L_DIM + r0 + 8] = d[3];
            }
            #pragma unroll
            for (int f = 0; f < 4; f++) {
                if (fabsf(d[f] - 0.1f) < BANDW) {
                    int rr = r0 + (f >> 1) * 8;
                    int cc = c0 + (f & 1);
                    int p = atomicAdd(&g_cnt, 1);
                    if (p < MAXB) g_list[p] = make_int2(rr, cc);
                    if (bx != by) {
                        p = atomicAdd(&g_cnt, 1);
                        if (p < MAXB) g_list[p] = make_int2(cc, rr);
                    }
                }
            }
        }
}

// ===========================================================================
// Fixup: exact fp32 recompute, unroll-4, 4 accumulators (MLP)
// ===========================================================================
__global__ void zero_cnt() { g_cnt = 0; }

__global__ __launch_bounds__(256) void fixup_band(
    const float* __restrict__ Z, float* __restrict__ S)
{
    const int wglobal = blockIdx.x * 8 + (threadIdx.x >> 5);
    const int lid = threadIdx.x & 31;
    const int nw = gridDim.x * 8;
    int cnt = g_cnt; if (cnt > MAXB) cnt = MAXB;
    for (int e = wglobal; e < cnt; e += nw) {
        int2 ij = g_list[e];
        const float4* a = (const float4*)(Z + (size_t)ij.x * KBIG);
        const float4* b = (const float4*)(Z + (size_t)ij.y * KBIG);
        float s0 = 0.f, s1 = 0.f, s2 = 0.f, s3 = 0.f;
        // KBIG/4 = 1200 float4 pairs: 9 x (4 x 32) = 1152, tail 48
        int k = lid;
        #pragma unroll 1
        for (int it = 0; it < 9; it++) {
            float4 a0 = a[k], a1 = a[k + 32], a2 = a[k + 64], a3 = a[k + 96];
            float4 b0 = b[k], b1 = b[k + 32], b2 = b[k + 64], b3 = b[k + 96];
            s0 = fmaf(a0.x, b0.x, fmaf(a0.y, b0.y, fmaf(a0.z, b0.z, fmaf(a0.w, b0.w, s0))));
            s1 = fmaf(a1.x, b1.x, fmaf(a1.y, b1.y, fmaf(a1.z, b1.z, fmaf(a1.w, b1.w, s1))));
            s2 = fmaf(a2.x, b2.x, fmaf(a2.y, b2.y, fmaf(a2.z, b2.z, fmaf(a2.w, b2.w, s2))));
            s3 = fmaf(a3.x, b3.x, fmaf(a3.y, b3.y, fmaf(a3.z, b3.z, fmaf(a3.w, b3.w, s3))));
            k += 128;
        }
        {
            float4 a0 = a[1152 + lid], b0 = b[1152 + lid];
            s0 = fmaf(a0.x, b0.x, fmaf(a0.y, b0.y, fmaf(a0.z, b0.z, fmaf(a0.w, b0.w, s0))));
            if (lid < 16) {
                float4 a1 = a[1184 + lid], b1 = b[1184 + lid];
                s1 = fmaf(a1.x, b1.x, fmaf(a1.y, b1.y, fmaf(a1.z, b1.z, fmaf(a1.w, b1.w, s1))));
            }
        }
        float sum = (s0 + s1) + (s2 + s3);
        #pragma unroll
        for (int o = 16; o; o >>= 1) sum += __shfl_xor_sync(0xffffffffu, sum, o);
        if (lid == 0) S[(size_t)ij.x * L_DIM + ij.y] = sum;
    }
}

// ===========================================================================
// Masked softmax -> adj bf16 hi/lo splits. One pass: row cached in registers.
// 256 threads, 8 values per thread.
// ===========================================================================
__global__ __launch_bounds__(256) void masked_softmax(
    const float* __restrict__ S,
    __nv_bfloat16* __restrict__ Phi, __nv_bfloat16* __restrict__ Plo)
{
    __shared__ float red[8];
    const int r   = blockIdx.x;
    const int tid = threadIdx.x;
    const float* row = S + (size_t)r * L_DIM;

    float v[8];
    #pragma unroll
    for (int i = 0; i < 8; i++) v[i] = row[tid + i * 256];

    float m = -1e30f;
    #pragma unroll
    for (int i = 0; i < 8; i++)
        if (v[i] >= 0.1f) m = fmaxf(m, v[i]);
    #pragma unroll
    for (int o = 16; o; o >>= 1) m = fmaxf(m, __shfl_xor_sync(0xffffffffu, m, o));
    if ((tid & 31) == 0) red[tid >> 5] = m;
    __syncthreads();
    float M = fmaxf(fmaxf(fmaxf(red[0], red[1]), fmaxf(red[2], red[3])),
                    fmaxf(fmaxf(red[4], red[5]), fmaxf(red[6], red[7])));
    __syncthreads();

    float sum = 0.f;
    #pragma unroll
    for (int i = 0; i < 8; i++) {
        v[i] = (v[i] >= 0.1f) ? expf(v[i] - M) : 0.f;
        sum += v[i];
    }
    #pragma unroll
    for (int o = 16; o; o >>= 1) sum += __shfl_xor_sync(0xffffffffu, sum, o);
    if ((tid & 31) == 0) red[tid >> 5] = sum;
    __syncthreads();
    float T = red[0] + red[1] + red[2] + red[3] +
              red[4] + red[5] + red[6] + red[7];
    float inv = 1.f / T;

    #pragma unroll
    for (int i = 0; i < 8; i++) {
        float p = v[i] * inv;
        __nv_bfloat16 hb = __float2bfloat16(p);
        Phi[(size_t)r * L_DIM + tid + i * 256] = hb;
        Plo[(size_t)r * L_DIM + tid + i * 256] =
            __float2bfloat16(p - __bfloat162float(hb));
    }
}

// ===========================================================================
// gcn_mma: C = relu(A @ B^T), A = adj hi/lo [2048 x 2048 K], B = Tt hi/lo
// [512 x 2048 K], C fp32 [2048 x 512]. 3-pass hi/lo (operands not normalized).
// ===========================================================================
#define GA_B 16384
#define GB_B 8192
#define GSTAGE_B (2 * GA_B + 2 * GB_B)
#define GCN_SMEM (3 * GSTAGE_B + 128)

__global__ void __launch_bounds__(256, 1) gcn_mma(
    const __nv_bfloat16* __restrict__ Ahi, const __nv_bfloat16* __restrict__ Alo,
    const __nv_bfloat16* __restrict__ Bhi, const __nv_bfloat16* __restrict__ Blo,
    float* __restrict__ C)
{
    const int K = L_DIM;
    extern __shared__ char smem_raw[];
    const uint32_t sb = (smem_u32(smem_raw) + 127u) & ~127u;

    const int tid  = threadIdx.x;
    const int wid  = tid >> 5, lane = tid & 31;
    const int bm = blockIdx.y << 7;
    const int bn = blockIdx.x << 6;
    const int wm = wid >> 2, wn = wid & 3;

    float acc[4][2][4];
    #pragma unroll
    for (int mt = 0; mt < 4; mt++)
        #pragma unroll
        for (int nt = 0; nt < 2; nt++)
            #pragma unroll
            for (int f = 0; f < 4; f++) acc[mt][nt][f] = 0.f;

    uint32_t offA[4][4], offB[4];
    #pragma unroll
    for (int mt = 0; mt < 4; mt++) {
        int r  = wm * 64 + mt * 16 + (lane & 15);
        int r7 = r & 7;
        #pragma unroll
        for (int ks = 0; ks < 4; ks++) {
            int ch = ks * 2 + (lane >> 4);
            offA[mt][ks] = r * 128 + ((ch ^ r7) << 4);
        }
    }
    {
        int ntl = (lane >> 4) & 1;
        int r   = wn * 16 + ntl * 8 + (lane & 7);
        int r7  = r & 7;
        #pragma unroll
        for (int ks = 0; ks < 4; ks++) {
            int ch = ks * 2 + ((lane >> 3) & 1);
            offB[ks] = r * 128 + ((ch ^ r7) << 4);
        }
    }

    uint32_t dstA[4]; int srcA[4];
    #pragma unroll
    for (int t = 0; t < 4; t++) {
        int idx = tid + t * 256;
        int r = idx >> 3, ch = idx & 7;
        dstA[t] = (uint32_t)(r * 128 + ((ch ^ (r & 7)) << 4));
        srcA[t] = (bm + r) * K + ch * 8;
    }
    uint32_t dstB[2]; int srcB[2];
    #pragma unroll
    for (int t = 0; t < 2; t++) {
        int idx = tid + t * 256;
        int r = idx >> 3, ch = idx & 7;
        dstB[t] = (uint32_t)(r * 128 + ((ch ^ (r & 7)) << 4));
        srcB[t] = (bn + r) * K + ch * 8;
    }

    auto cp_stage = [&](int s, int kt) {
        const int k0 = kt << 6;
        const uint32_t base = sb + (uint32_t)s * GSTAGE_B;
        #pragma unroll
        for (int t = 0; t < 4; t++) {
            CP_ASYNC16(base + dstA[t],        Ahi + srcA[t] + k0);
            CP_ASYNC16(base + GA_B + dstA[t], Alo + srcA[t] + k0);
        }
        #pragma unroll
        for (int t = 0; t < 2; t++) {
            CP_ASYNC16(base + 2 * GA_B + dstB[t],        Bhi + srcB[t] + k0);
            CP_ASYNC16(base + 2 * GA_B + GB_B + dstB[t], Blo + srcB[t] + k0);
        }
        CP_COMMIT();
    };

    auto compute = [&](int s) {
        const uint32_t pa = sb + (uint32_t)s * GSTAGE_B;
        #pragma unroll
        for (int ks = 0; ks < 4; ks++) {
            uint32_t ahi[4][4], alo[4][4], bh[4], bl[4];
            #pragma unroll
            for (int mt = 0; mt < 4; mt++) {
                ldsm_x4(ahi[mt], pa + offA[mt][ks]);
                ldsm_x4(alo[mt], pa + GA_B + offA[mt][ks]);
            }
            ldsm_x4(bh, pa + 2 * GA_B + offB[ks]);
            ldsm_x4(bl, pa + 2 * GA_B + GB_B + offB[ks]);
            #pragma unroll
            for (int nt = 0; nt < 2; nt++)
                #pragma unroll
                for (int mt = 0; mt < 4; mt++) {
                    mma_bf16(acc[mt][nt], ahi[mt], bh + 2 * nt);
                    mma_bf16(acc[mt][nt], ahi[mt], bl + 2 * nt);
                    mma_bf16(acc[mt][nt], alo[mt], bh + 2 * nt);
                }
        }
    };

    const int NKT = K / 64;
    cp_stage(0, 0);
    cp_stage(1, 1);
    int sc = 0, s2 = 2;
    for (int kt = 0; kt < NKT; kt++) {
        if (kt + 1 < NKT) { CP_WAIT(1); } else { CP_WAIT(0); }
        __syncthreads();
        if (kt + 2 < NKT) cp_stage(s2, kt + 2);
        compute(sc);
        if (++sc == 3) sc = 0;
        if (++s2 == 3) s2 = 0;
    }

    #pragma unroll
    for (int mt = 0; mt < 4; mt++)
        #pragma unroll
        for (int nt = 0; nt < 2; nt++) {
            const int r0 = bm + wm * 64 + mt * 16 + (lane >> 2);
            const int c0 = bn + wn * 16 + nt * 8 + (lane & 3) * 2;
            const float* d = acc[mt][nt];
            *(float2*)(C + (size_t)r0 * E_DIM + c0) =
                make_float2(fmaxf(d[0], 0.f), fmaxf(d[1], 0.f));
            *(float2*)(C + (size_t)(r0 + 8) * E_DIM + c0) =
                make_float2(fmaxf(d[2], 0.f), fmaxf(d[3], 0.f));
        }
}

// ===========================================================================
// SIMT GEMM: C = A @ B, epilogue writes TRANSPOSED bf16 hi/lo splits
// ===========================================================================
__global__ __launch_bounds__(256, 2) void gemm_split_t(
    const float* __restrict__ A, const float* __restrict__ B,
    __nv_bfloat16* __restrict__ Chi, __nv_bfloat16* __restrict__ Clo,
    int M, int N, int K)
{
    constexpr int BM = 128, BN = 64;
    constexpr int TM = 8, TN = 4;
    constexpr int NA = 2, NB = 1;

    __shared__ float As[2][16][BM + 4];
    __shared__ float Bs[2][16][BN + 4];

    const int bm = blockIdx.y * BM;
    const int bn = blockIdx.x * BN;
    const int tid = threadIdx.x;
    const int tx  = tid & 15;
    const int ty  = tid >> 4;

    float acc[TM][TN];
    #pragma unroll
    for (int i = 0; i < TM; i++)
        #pragma unroll
        for (int j = 0; j < TN; j++) acc[i][j] = 0.f;

    float4 ra[NA], rb[NB];

    #define LD_A(k0)                                                          \
        _Pragma("unroll")                                                     \
        for (int t = 0; t < NA; t++) {                                        \
            int idx = tid + t * 256;                                          \
            int rr = idx >> 2, cc = (idx & 3) << 2;                           \
            ra[t] = *(const float4*)(A + (size_t)(bm + rr) * K + (k0) + cc);  \
        }
    #define LD_B(k0)                                                          \
        _Pragma("unroll")                                                     \
        for (int t = 0; t < NB; t++) {                                        \
            int idx = tid + t * 256;                                          \
            int rr = idx / (BN / 4), cc = (idx % (BN / 4)) << 2;              \
            rb[t] = *(const float4*)(B + (size_t)((k0) + rr) * N + bn + cc);  \
        }
    #define ST_A(buf)                                                         \
        _Pragma("unroll")                                                     \
        for (int t = 0; t < NA; t++) {                                        \
            int idx = tid + t * 256;                                          \
            int rr = idx >> 2, cc = (idx & 3) << 2;                           \
            As[buf][cc + 0][rr] = ra[t].x; As[buf][cc + 1][rr] = ra[t].y;     \
            As[buf][cc + 2][rr] = ra[t].z; As[buf][cc + 3][rr] = ra[t].w;     \
        }
    #define ST_B(buf)                                                         \
        _Pragma("unroll")                                                     \
        for (int t = 0; t < NB; t++) {                                        \
            int idx = tid + t * 256;                                          \
            int rr = idx / (BN / 4), cc = (idx % (BN / 4)) << 2;              \
            *(float4*)&Bs[buf][rr][cc] = rb[t];                               \
        }

    const int nk = K >> 4;
    LD_A(0); LD_B(0);
    ST_A(0); ST_B(0);
    __syncthreads();

    int cur = 0;
    for (int kt = 0; kt < nk; kt++) {
        if (kt + 1 < nk) { int k0 = (kt + 1) << 4; LD_A(k0); LD_B(k0); }
        #pragma unroll
        for (int kk = 0; kk < 16; kk++) {
            float a[TM], b[TN];
            #pragma unroll
            for (int i = 0; i < TM; i += 4)
                *(float4*)(a + i) = *(const float4*)&As[cur][kk][ty * TM + i];
            *(float4*)(b) = *(const float4*)&Bs[cur][kk][tx * TN];
            #pragma unroll
            for (int i = 0; i < TM; i++)
                #pragma unroll
                for (int j = 0; j < TN; j++)
                    acc[i][j] = fmaf(a[i], b[j], acc[i][j]);
        }
        if (kt + 1 < nk) { ST_A(cur ^ 1); ST_B(cur ^ 1); }
        __syncthreads();
        cur ^= 1;
    }

    #pragma unroll
    for (int j = 0; j < TN; j++) {
        size_t rowb = (size_t)(bn + tx * TN + j) * M + bm + ty * TM;
        #pragma unroll
        for (int i = 0; i < TM; i++) {
            float v = acc[i][j];
            __nv_bfloat16 hb = __float2bfloat16(v);
            Chi[rowb + i] = hb;
            Clo[rowb + i] = __float2bfloat16(v - __bfloat162float(hb));
        }
    }
    #undef LD_A
    #undef LD_B
    #undef ST_A
    #undef ST_B
}

// ===========================================================================
// Launch
// ===========================================================================
extern "C" void kernel_launch(void* const* d_in, const int* in_sizes, int n_in,
                              void* d_out, int out_size)
{
    const float* Lemb = (const float*)d_in[0];
    const float* Xpt  = (const float*)d_in[1];
    const float* Wpt  = (const float*)d_in[2];
    const float* W0   = (const float*)d_in[3];
    const float* W1   = (const float*)d_in[4];
    float* out = (float*)d_out;

    float *Z, *S, *T0, *X1, *T1;
    __nv_bfloat16 *Zhi, *Zlo;
    cudaGetSymbolAddress((void**)&Z,   g_Z);
    cudaGetSymbolAddress((void**)&Zhi, g_Zhi);
    cudaGetSymbolAddress((void**)&Zlo, g_Zlo);
    cudaGetSymbolAddress((void**)&S,   g_S);
    cudaGetSymbolAddress((void**)&T0,  g_T0);
    cudaGetSymbolAddress((void**)&X1,  g_X1);
    cudaGetSymbolAddress((void**)&T1,  g_T1);

    __nv_bfloat16* Phi = Zhi;
    __nv_bfloat16* Plo = Zlo;
    __nv_bfloat16* Tt_hi = (__nv_bfloat16*)T0;
    __nv_bfloat16* Tt_lo = (__nv_bfloat16*)T1;

    cudaFuncSetAttribute(zzt_mma, cudaFuncAttributeMaxDynamicSharedMemorySize,
                         ZZT_SMEM);
    cudaFuncSetAttribute(gcn_mma, cudaFuncAttributeMaxDynamicSharedMemorySize,
                         GCN_SMEM);

    zero_cnt<<<1, 1>>>();

    // 1) Z fp32 + Zhi bf16
    compute_z<<<L_DIM, 512>>>(Xpt, Wpt, Z, Zhi);

    // 2) scores = Z Z^T (single-pass bf16 mma), band scan fused
    zzt_mma<<<dim3(16, 16), 256, ZZT_SMEM>>>(Zhi, S);

    // 3) exact fp32 fixup of near-threshold entries
    fixup_band<<<128, 256>>>(Z, S);

    // 4) adj = softmax(threshold(scores)) -> bf16 hi/lo splits
    masked_softmax<<<L_DIM, 256>>>(S, Phi, Plo);

    // 5) T0t = (Lemb @ W0)^T as bf16 hi/lo
    gemm_split_t<<<dim3(E_DIM / 64, L_DIM / 128), 256>>>(
        Lemb, W0, Tt_hi, Tt_lo, L_DIM, E_DIM, E_DIM);

    // 6) X1 = relu(adj @ T0)
    gcn_mma<<<dim3(E_DIM / 64, L_DIM / 128), 256, GCN_SMEM>>>(
        Phi, Plo, Tt_hi, Tt_lo, X1);

    // 7) T1t = (X1 @ W1)^T as bf16 hi/lo
    gemm_split_t<<<dim3(E_DIM / 64, L_DIM / 128), 256>>>(
        X1, W1, Tt_hi, Tt_lo, L_DIM, E_DIM, E_DIM);

    // 8) out = relu(adj @ T1)
    gcn_mma<<<dim3(E_DIM / 64, L_DIM / 128), 256, GCN_SMEM>>>(
        Phi, Plo, Tt_hi, Tt_lo, out);
}

// round 8
// speedup vs baseline: 3.7396x; 1.3124x over previous
#include <cuda_runtime.h>
#include <cuda_fp16.h>
#include <math.h>
#include <stdint.h>

// Problem constants
#define L_DIM   2048
#define E_DIM   512
#define EPT_DIM 300
#define H_DIM   16
#define KBIG    (H_DIM * EPT_DIM)   // 4800

// Scratch (allocation-free rule: __device__ globals)
__device__ float  g_Z  [L_DIM * KBIG];      // fp32 Z (exact fixup)
__device__ __half g_Zh [L_DIM * KBIG];      // fp16 Z (zzt input)
__device__ float  g_S  [L_DIM * L_DIM];     // scores
__device__ __half g_Phi[L_DIM * L_DIM];     // adj hi
__device__ __half g_Plo[L_DIM * L_DIM];     // adj lo
__device__ __half g_Ahi[L_DIM * E_DIM];     // Lemb / X1 splits (A operand)
__device__ __half g_Alo[L_DIM * E_DIM];
__device__ __half g_Whi[E_DIM * E_DIM];     // W^T splits
__device__ __half g_Wlo[E_DIM * E_DIM];
__device__ __half g_Thi[E_DIM * L_DIM];     // T^T splits (B operand of gcn)
__device__ __half g_Tlo[E_DIM * L_DIM];

#define MAXB (1 << 18)
#define BANDW 1e-4f
__device__ int  g_cnt;
__device__ int2 g_list[MAXB];

// ===========================================================================
// Helpers
// ===========================================================================
__device__ __forceinline__ uint32_t smem_u32(const void* p) {
    uint32_t a;
    asm("{ .reg .u64 t; cvta.to.shared.u64 t, %1; cvt.u32.u64 %0, t; }"
        : "=r"(a) : "l"(p));
    return a;
}
__device__ __forceinline__ void ldsm_x4(uint32_t* r, uint32_t addr) {
    asm volatile("ldmatrix.sync.aligned.m8n8.x4.shared.b16 {%0,%1,%2,%3}, [%4];"
                 : "=r"(r[0]), "=r"(r[1]), "=r"(r[2]), "=r"(r[3]) : "r"(addr));
}
__device__ __forceinline__ void mma_f16(float* d, const uint32_t* a,
                                        const uint32_t* b) {
    asm volatile("mma.sync.aligned.m16n8k16.row.col.f32.f16.f16.f32 "
                 "{%0,%1,%2,%3}, {%4,%5,%6,%7}, {%8,%9}, {%0,%1,%2,%3};"
                 : "+f"(d[0]), "+f"(d[1]), "+f"(d[2]), "+f"(d[3])
                 : "r"(a[0]), "r"(a[1]), "r"(a[2]), "r"(a[3]),
                   "r"(b[0]), "r"(b[1]));
}
#define CP_ASYNC16(dst, src) \
    asm volatile("cp.async.cg.shared.global [%0], [%1], 16;" \
                 :: "r"(dst), "l"(src))
#define CP_COMMIT()  asm volatile("cp.async.commit_group;" ::: "memory")
#define CP_WAIT(N)   asm volatile("cp.async.wait_group " #N ";" ::: "memory")

__device__ __forceinline__ void split16(float v, __half& hi, __half& lo) {
    hi = __float2half_rn(v);
    lo = __float2half_rn(v - __half2float(hi));
}

// ===========================================================================
// Kernel 1: Z (fp32) + Zh (fp16). Warp per (l, h).
// ===========================================================================
__global__ __launch_bounds__(512) void compute_z(
    const float* __restrict__ xpt, const float* __restrict__ Wpt,
    float* __restrict__ Z, __half* __restrict__ Zh)
{
    const int l    = blockIdx.x;
    const int h    = threadIdx.x >> 5;
    const int lane = threadIdx.x & 31;

    const float* xrow = xpt + (size_t)l * EPT_DIM;
    const float* wrow = Wpt + h * EPT_DIM;

    float v[10];
    float ss = 0.f;
    #pragma unroll
    for (int i = 0; i < 10; i++) {
        int e = lane + i * 32;
        float vv = 0.f;
        if (e < EPT_DIM) {
            float w = wrow[e];
            vv = xrow[e] * w * w;
        }
        v[i] = vv;
        ss += vv * vv;
    }
    #pragma unroll
    for (int o = 16; o; o >>= 1) ss += __shfl_xor_sync(0xffffffffu, ss, o);
    float inv = 0.25f / fmaxf(sqrtf(ss), 1e-12f);

    size_t base = (size_t)l * KBIG + h * EPT_DIM;
    #pragma unroll
    for (int i = 0; i < 10; i++) {
        int e = lane + i * 32;
        if (e < EPT_DIM) {
            float val = v[i] * inv;
            Z[base + e]  = val;
            Zh[base + e] = __float2half_rn(val);
        }
    }
}

// ===========================================================================
// Kernel 2: ZZ^T single-pass fp16 mma.sync; 3-stage cp.async; symmetric.
// ===========================================================================
#define TILE_B   16384
#define STAGE_B  (2 * TILE_B)
#define ZZT_SMEM (3 * STAGE_B + 128)

__global__ void __launch_bounds__(256, 1) zzt_mma(
    const __half* __restrict__ Zh, float* __restrict__ S)
{
    const int bx = blockIdx.x, by = blockIdx.y;
    if (bx < by) return;
    extern __shared__ char smem_raw[];
    const uint32_t sb = (smem_u32(smem_raw) + 127u) & ~127u;

    const int tid  = threadIdx.x;
    const int wid  = tid >> 5, lane = tid & 31;
    const int bm = by << 7, bn = bx << 7;
    const int wm = wid >> 2, wn = wid & 3;

    float acc[4][4][4];
    #pragma unroll
    for (int mt = 0; mt < 4; mt++)
        #pragma unroll
        for (int nt = 0; nt < 4; nt++)
            #pragma unroll
            for (int f = 0; f < 4; f++) acc[mt][nt][f] = 0.f;

    uint32_t offA[4][4], offBp[2][4];
    #pragma unroll
    for (int mt = 0; mt < 4; mt++) {
        int r  = wm * 64 + mt * 16 + (lane & 15);
        int r7 = r & 7;
        #pragma unroll
        for (int ks = 0; ks < 4; ks++) {
            int ch = ks * 2 + (lane >> 4);
            offA[mt][ks] = r * 128 + ((ch ^ r7) << 4);
        }
    }
    #pragma unroll
    for (int p = 0; p < 2; p++) {
        int ntl = p * 2 + ((lane >> 4) & 1);
        int r   = wn * 32 + ntl * 8 + (lane & 7);
        int r7  = r & 7;
        #pragma unroll
        for (int ks = 0; ks < 4; ks++) {
            int ch = ks * 2 + ((lane >> 3) & 1);
            offBp[p][ks] = r * 128 + ((ch ^ r7) << 4);
        }
    }

    uint32_t dstoff[4];
    int      srcA[4], srcB[4];
    #pragma unroll
    for (int t = 0; t < 4; t++) {
        int idx = tid + t * 256;
        int r = idx >> 3, ch = idx & 7;
        dstoff[t] = (uint32_t)(r * 128 + ((ch ^ (r & 7)) << 4));
        srcA[t] = (bm + r) * KBIG + ch * 8;
        srcB[t] = (bn + r) * KBIG + ch * 8;
    }

    auto cp_stage = [&](int s, int kt) {
        const int k0 = kt << 6;
        const uint32_t base = sb + (uint32_t)s * STAGE_B;
        #pragma unroll
        for (int t = 0; t < 4; t++) {
            CP_ASYNC16(base + dstoff[t],          Zh + srcA[t] + k0);
            CP_ASYNC16(base + TILE_B + dstoff[t], Zh + srcB[t] + k0);
        }
        CP_COMMIT();
    };

    auto compute = [&](int s) {
        const uint32_t pa = sb + (uint32_t)s * STAGE_B;
        #pragma unroll
        for (int ks = 0; ks < 4; ks++) {
            uint32_t ah[4][4];
            #pragma unroll
            for (int mt = 0; mt < 4; mt++)
                ldsm_x4(ah[mt], pa + offA[mt][ks]);
            #pragma unroll
            for (int p = 0; p < 2; p++) {
                uint32_t bh[4];
                ldsm_x4(bh, pa + TILE_B + offBp[p][ks]);
                #pragma unroll
                for (int half = 0; half < 2; half++) {
                    int nt = p * 2 + half;
                    #pragma unroll
                    for (int mt = 0; mt < 4; mt++)
                        mma_f16(acc[mt][nt], ah[mt], bh + 2 * half);
                }
            }
        }
    };

    const int NKT = KBIG / 64;   // 75
    cp_stage(0, 0);
    cp_stage(1, 1);
    int sc = 0, s2 = 2;
    for (int kt = 0; kt < NKT; kt++) {
        if (kt + 1 < NKT) { CP_WAIT(1); } else { CP_WAIT(0); }
        __syncthreads();
        if (kt + 2 < NKT) cp_stage(s2, kt + 2);
        compute(sc);
        if (++sc == 3) sc = 0;
        if (++s2 == 3) s2 = 0;
    }

    #pragma unroll
    for (int mt = 0; mt < 4; mt++)
        #pragma unroll
        for (int nt = 0; nt < 4; nt++) {
            const int r0 = bm + wm * 64 + mt * 16 + (lane >> 2);
            const int c0 = bn + wn * 32 + nt * 8 + (lane & 3) * 2;
            const float* d = acc[mt][nt];
            *(float2*)(S + (size_t)r0 * L_DIM + c0)       = make_float2(d[0], d[1]);
            *(float2*)(S + (size_t)(r0 + 8) * L_DIM + c0) = make_float2(d[2], d[3]);
            if (bx != by) {
                S[(size_t)c0 * L_DIM + r0]           = d[0];
                S[(size_t)(c0 + 1) * L_DIM + r0]     = d[1];
                S[(size_t)c0 * L_DIM + r0 + 8]       = d[2];
                S[(size_t)(c0 + 1) * L_DIM + r0 + 8] = d[3];
            }
            #pragma unroll
            for (int f = 0; f < 4; f++) {
                if (fabsf(d[f] - 0.1f) < BANDW) {
                    int rr = r0 + (f >> 1) * 8;
                    int cc = c0 + (f & 1);
                    int p = atomicAdd(&g_cnt, 1);
                    if (p < MAXB) g_list[p] = make_int2(rr, cc);
                    if (bx != by) {
                        p = atomicAdd(&g_cnt, 1);
                        if (p < MAXB) g_list[p] = make_int2(cc, rr);
                    }
                }
            }
        }
}

// ===========================================================================
// Fixup: exact fp32 recompute, one CTA (128 threads) per entry
// ===========================================================================
__global__ void zero_cnt() { g_cnt = 0; }

__global__ __launch_bounds__(128) void fixup_band(
    const float* __restrict__ Z, float* __restrict__ S)
{
    __shared__ float red[4];
    const int tid = threadIdx.x, lid = tid & 31, wid = tid >> 5;
    int cnt = g_cnt; if (cnt > MAXB) cnt = MAXB;
    for (int e = blockIdx.x; e < cnt; e += gridDim.x) {
        int2 ij = g_list[e];
        const float4* a = (const float4*)(Z + (size_t)ij.x * KBIG);
        const float4* b = (const float4*)(Z + (size_t)ij.y * KBIG);
        float s = 0.f;
        #pragma unroll 5
        for (int k = tid; k < KBIG / 4; k += 128) {
            float4 av = a[k], bv = b[k];
            s = fmaf(av.x, bv.x, fmaf(av.y, bv.y,
                fmaf(av.z, bv.z, fmaf(av.w, bv.w, s))));
        }
        #pragma unroll
        for (int o = 16; o; o >>= 1) s += __shfl_xor_sync(0xffffffffu, s, o);
        if (lid == 0) red[wid] = s;
        __syncthreads();
        if (tid == 0)
            S[(size_t)ij.x * L_DIM + ij.y] = red[0] + red[1] + red[2] + red[3];
        __syncthreads();
    }
}

// ===========================================================================
// Masked softmax -> adj fp16 hi/lo splits (one pass, row in registers)
// ===========================================================================
__global__ __launch_bounds__(256) void masked_softmax(
    const float* __restrict__ S,
    __half* __restrict__ Phi, __half* __restrict__ Plo)
{
    __shared__ float red[8];
    const int r   = blockIdx.x;
    const int tid = threadIdx.x;
    const float* row = S + (size_t)r * L_DIM;

    float v[8];
    #pragma unroll
    for (int i = 0; i < 8; i++) v[i] = row[tid + i * 256];

    float m = -1e30f;
    #pragma unroll
    for (int i = 0; i < 8; i++)
        if (v[i] >= 0.1f) m = fmaxf(m, v[i]);
    #pragma unroll
    for (int o = 16; o; o >>= 1) m = fmaxf(m, __shfl_xor_sync(0xffffffffu, m, o));
    if ((tid & 31) == 0) red[tid >> 5] = m;
    __syncthreads();
    float M = fmaxf(fmaxf(fmaxf(red[0], red[1]), fmaxf(red[2], red[3])),
                    fmaxf(fmaxf(red[4], red[5]), fmaxf(red[6], red[7])));
    __syncthreads();

    float sum = 0.f;
    #pragma unroll
    for (int i = 0; i < 8; i++) {
        v[i] = (v[i] >= 0.1f) ? expf(v[i] - M) : 0.f;
        sum += v[i];
    }
    #pragma unroll
    for (int o = 16; o; o >>= 1) sum += __shfl_xor_sync(0xffffffffu, sum, o);
    if ((tid & 31) == 0) red[tid >> 5] = sum;
    __syncthreads();
    float T = red[0] + red[1] + red[2] + red[3] +
              red[4] + red[5] + red[6] + red[7];
    float inv = 1.f / T;

    #pragma unroll
    for (int i = 0; i < 8; i++) {
        float p = v[i] * inv;
        __half hb, lb;
        split16(p, hb, lb);
        Phi[(size_t)r * L_DIM + tid + i * 256] = hb;
        Plo[(size_t)r * L_DIM + tid + i * 256] = lb;
    }
}

// ===========================================================================
// Conversions: row split (fp32 -> fp16 hi/lo) and transpose split (W -> W^T)
// ===========================================================================
__global__ __launch_bounds__(256) void split_rows(
    const float* __restrict__ A, __half* __restrict__ Ahi,
    __half* __restrict__ Alo, int n)
{
    int i = blockIdx.x * 256 + threadIdx.x;
    if (i < n) {
        __half hb, lb;
        split16(A[i], hb, lb);
        Ahi[i] = hb; Alo[i] = lb;
    }
}

__global__ __launch_bounds__(256) void conv_wt(
    const float* __restrict__ W, __half* __restrict__ Whi,
    __half* __restrict__ Wlo)
{
    __shared__ float t[32][33];
    const int bx = blockIdx.x * 32, by = blockIdx.y * 32;
    const int x = threadIdx.x & 31, y4 = (threadIdx.x >> 5) * 4;
    #pragma unroll
    for (int i = 0; i < 4; i++)
        t[y4 + i][x] = W[(size_t)(by + y4 + i) * E_DIM + bx + x];
    __syncthreads();
    #pragma unroll
    for (int i = 0; i < 4; i++) {
        float v = t[x][y4 + i];           // W[by+x][bx+y4+i]
        __half hb, lb;
        split16(v, hb, lb);
        size_t o = (size_t)(bx + y4 + i) * E_DIM + by + x;   // Wt[n][k]
        Whi[o] = hb; Wlo[o] = lb;
    }
}

// ===========================================================================
// split_mma: T = A @ W (A [M=2048,K=512] hi/lo, W^T [N=512,K=512] hi/lo),
// 3-pass fp16, writes T TRANSPOSED as fp16 hi/lo [N, M]. No relu.
// ===========================================================================
#define GA_B 16384
#define GB_B 8192
#define GSTAGE_B (2 * GA_B + 2 * GB_B)
#define GCN_SMEM (3 * GSTAGE_B + 128)

__global__ void __launch_bounds__(256, 1) split_mma(
    const __half* __restrict__ Ahi, const __half* __restrict__ Alo,
    const __half* __restrict__ Bhi, const __half* __restrict__ Blo,
    __half* __restrict__ Thi, __half* __restrict__ Tlo)
{
    const int K = E_DIM;   // 512
    extern __shared__ char smem_raw[];
    const uint32_t sb = (smem_u32(smem_raw) + 127u) & ~127u;

    const int tid  = threadIdx.x;
    const int wid  = tid >> 5, lane = tid & 31;
    const int bm = blockIdx.y << 7;
    const int bn = blockIdx.x << 6;
    const int wm = wid >> 2, wn = wid & 3;

    float acc[4][2][4];
    #pragma unroll
    for (int mt = 0; mt < 4; mt++)
        #pragma unroll
        for (int nt = 0; nt < 2; nt++)
            #pragma unroll
            for (int f = 0; f < 4; f++) acc[mt][nt][f] = 0.f;

    uint32_t offA[4][4], offB[4];
    #pragma unroll
    for (int mt = 0; mt < 4; mt++) {
        int r  = wm * 64 + mt * 16 + (lane & 15);
        int r7 = r & 7;
        #pragma unroll
        for (int ks = 0; ks < 4; ks++) {
            int ch = ks * 2 + (lane >> 4);
            offA[mt][ks] = r * 128 + ((ch ^ r7) << 4);
        }
    }
    {
        int ntl = (lane >> 4) & 1;
        int r   = wn * 16 + ntl * 8 + (lane & 7);
        int r7  = r & 7;
        #pragma unroll
        for (int ks = 0; ks < 4; ks++) {
            int ch = ks * 2 + ((lane >> 3) & 1);
            offB[ks] = r * 128 + ((ch ^ r7) << 4);
        }
    }

    uint32_t dstA[4]; int srcA[4];
    #pragma unroll
    for (int t = 0; t < 4; t++) {
        int idx = tid + t * 256;
        int r = idx >> 3, ch = idx & 7;
        dstA[t] = (uint32_t)(r * 128 + ((ch ^ (r & 7)) << 4));
        srcA[t] = (bm + r) * K + ch * 8;
    }
    uint32_t dstB[2]; int srcB[2];
    #pragma unroll
    for (int t = 0; t < 2; t++) {
        int idx = tid + t * 256;
        int r = idx >> 3, ch = idx & 7;
        dstB[t] = (uint32_t)(r * 128 + ((ch ^ (r & 7)) << 4));
        srcB[t] = (bn + r) * K + ch * 8;
    }

    auto cp_stage = [&](int s, int kt) {
        const int k0 = kt << 6;
        const uint32_t base = sb + (uint32_t)s * GSTAGE_B;
        #pragma unroll
        for (int t = 0; t < 4; t++) {
            CP_ASYNC16(base + dstA[t],        Ahi + srcA[t] + k0);
            CP_ASYNC16(base + GA_B + dstA[t], Alo + srcA[t] + k0);
        }
        #pragma unroll
        for (int t = 0; t < 2; t++) {
            CP_ASYNC16(base + 2 * GA_B + dstB[t],        Bhi + srcB[t] + k0);
            CP_ASYNC16(base + 2 * GA_B + GB_B + dstB[t], Blo + srcB[t] + k0);
        }
        CP_COMMIT();
    };

    auto compute = [&](int s) {
        const uint32_t pa = sb + (uint32_t)s * GSTAGE_B;
        #pragma unroll
        for (int ks = 0; ks < 4; ks++) {
            uint32_t ahi[4][4], alo[4][4], bh[4], bl[4];
            #pragma unroll
            for (int mt = 0; mt < 4; mt++) {
                ldsm_x4(ahi[mt], pa + offA[mt][ks]);
                ldsm_x4(alo[mt], pa + GA_B + offA[mt][ks]);
            }
            ldsm_x4(bh, pa + 2 * GA_B + offB[ks]);
            ldsm_x4(bl, pa + 2 * GA_B + GB_B + offB[ks]);
            #pragma unroll
            for (int nt = 0; nt < 2; nt++)
                #pragma unroll
                for (int mt = 0; mt < 4; mt++) {
                    mma_f16(acc[mt][nt], ahi[mt], bh + 2 * nt);
                    mma_f16(acc[mt][nt], ahi[mt], bl + 2 * nt);
                    mma_f16(acc[mt][nt], alo[mt], bh + 2 * nt);
                }
        }
    };

    const int NKT = K / 64;   // 8
    cp_stage(0, 0);
    cp_stage(1, 1);
    int sc = 0, s2 = 2;
    for (int kt = 0; kt < NKT; kt++) {
        if (kt + 1 < NKT) { CP_WAIT(1); } else { CP_WAIT(0); }
        __syncthreads();
        if (kt + 2 < NKT) cp_stage(s2, kt + 2);
        compute(sc);
        if (++sc == 3) sc = 0;
        if (++s2 == 3) s2 = 0;
    }

    // transposed split epilogue: Tt[n][m], ld = L_DIM
    #pragma unroll
    for (int mt = 0; mt < 4; mt++)
        #pragma unroll
        for (int nt = 0; nt < 2; nt++) {
            const int r0 = bm + wm * 64 + mt * 16 + (lane >> 2);
            const int c0 = bn + wn * 16 + nt * 8 + (lane & 3) * 2;
            const float* d = acc[mt][nt];
            #pragma unroll
            for (int f = 0; f < 4; f++) {
                int rr = r0 + (f >> 1) * 8;
                int cc = c0 + (f & 1);
                __half hb, lb;
                split16(d[f], hb, lb);
                Thi[(size_t)cc * L_DIM + rr] = hb;
                Tlo[(size_t)cc * L_DIM + rr] = lb;
            }
        }
}

// ===========================================================================
// gcn_mma: C = relu(P @ Tt^T). OUT_SPLIT=1 -> fp16 hi/lo row-major (X1);
// OUT_SPLIT=0 -> fp32 out.
// ===========================================================================
template <int OUT_SPLIT>
__global__ void __launch_bounds__(256, 1) gcn_mma(
    const __half* __restrict__ Ahi, const __half* __restrict__ Alo,
    const __half* __restrict__ Bhi, const __half* __restrict__ Blo,
    float* __restrict__ C, __half* __restrict__ Xhi, __half* __restrict__ Xlo)
{
    const int K = L_DIM;   // 2048
    extern __shared__ char smem_raw[];
    const uint32_t sb = (smem_u32(smem_raw) + 127u) & ~127u;

    const int tid  = threadIdx.x;
    const int wid  = tid >> 5, lane = tid & 31;
    const int bm = blockIdx.y << 7;
    const int bn = blockIdx.x << 6;
    const int wm = wid >> 2, wn = wid & 3;

    float acc[4][2][4];
    #pragma unroll
    for (int mt = 0; mt < 4; mt++)
        #pragma unroll
        for (int nt = 0; nt < 2; nt++)
            #pragma unroll
            for (int f = 0; f < 4; f++) acc[mt][nt][f] = 0.f;

    uint32_t offA[4][4], offB[4];
    #pragma unroll
    for (int mt = 0; mt < 4; mt++) {
        int r  = wm * 64 + mt * 16 + (lane & 15);
        int r7 = r & 7;
        #pragma unroll
        for (int ks = 0; ks < 4; ks++) {
            int ch = ks * 2 + (lane >> 4);
            offA[mt][ks] = r * 128 + ((ch ^ r7) << 4);
        }
    }
    {
        int ntl = (lane >> 4) & 1;
        int r   = wn * 16 + ntl * 8 + (lane & 7);
        int r7  = r & 7;
        #pragma unroll
        for (int ks = 0; ks < 4; ks++) {
            int ch = ks * 2 + ((lane >> 3) & 1);
            offB[ks] = r * 128 + ((ch ^ r7) << 4);
        }
    }

    uint32_t dstA[4]; int srcA[4];
    #pragma unroll
    for (int t = 0; t < 4; t++) {
        int idx = tid + t * 256;
        int r = idx >> 3, ch = idx & 7;
        dstA[t] = (uint32_t)(r * 128 + ((ch ^ (r & 7)) << 4));
        srcA[t] = (bm + r) * K + ch * 8;
    }
    uint32_t dstB[2]; int srcB[2];
    #pragma unroll
    for (int t = 0; t < 2; t++) {
        int idx = tid + t * 256;
        int r = idx >> 3, ch = idx & 7;
        dstB[t] = (uint32_t)(r * 128 + ((ch ^ (r & 7)) << 4));
        srcB[t] = (bn + r) * K + ch * 8;
    }

    auto cp_stage = [&](int s, int kt) {
        const int k0 = kt << 6;
        const uint32_t base = sb + (uint32_t)s * GSTAGE_B;
        #pragma unroll
        for (int t = 0; t < 4; t++) {
            CP_ASYNC16(base + dstA[t],        Ahi + srcA[t] + k0);
            CP_ASYNC16(base + GA_B + dstA[t], Alo + srcA[t] + k0);
        }
        #pragma unroll
        for (int t = 0; t < 2; t++) {
            CP_ASYNC16(base + 2 * GA_B + dstB[t],        Bhi + srcB[t] + k0);
            CP_ASYNC16(base + 2 * GA_B + GB_B + dstB[t], Blo + srcB[t] + k0);
        }
        CP_COMMIT();
    };

    auto compute = [&](int s) {
        const uint32_t pa = sb + (uint32_t)s * GSTAGE_B;
        #pragma unroll
        for (int ks = 0; ks < 4; ks++) {
            uint32_t ahi[4][4], alo[4][4], bh[4], bl[4];
            #pragma unroll
            for (int mt = 0; mt < 4; mt++) {
                ldsm_x4(ahi[mt], pa + offA[mt][ks]);
                ldsm_x4(alo[mt], pa + GA_B + offA[mt][ks]);
            }
            ldsm_x4(bh, pa + 2 * GA_B + offB[ks]);
            ldsm_x4(bl, pa + 2 * GA_B + GB_B + offB[ks]);
            #pragma unroll
            for (int nt = 0; nt < 2; nt++)
                #pragma unroll
                for (int mt = 0; mt < 4; mt++) {
                    mma_f16(acc[mt][nt], ahi[mt], bh + 2 * nt);
                    mma_f16(acc[mt][nt], ahi[mt], bl + 2 * nt);
                    mma_f16(acc[mt][nt], alo[mt], bh + 2 * nt);
                }
        }
    };

    const int NKT = K / 64;   // 32
    cp_stage(0, 0);
    cp_stage(1, 1);
    int sc = 0, s2 = 2;
    for (int kt = 0; kt < NKT; kt++) {
        if (kt + 1 < NKT) { CP_WAIT(1); } else { CP_WAIT(0); }
        __syncthreads();
        if (kt + 2 < NKT) cp_stage(s2, kt + 2);
        compute(sc);
        if (++sc == 3) sc = 0;
        if (++s2 == 3) s2 = 0;
    }

    #pragma unroll
    for (int mt = 0; mt < 4; mt++)
        #pragma unroll
        for (int nt = 0; nt < 2; nt++) {
            const int r0 = bm + wm * 64 + mt * 16 + (lane >> 2);
            const int c0 = bn + wn * 16 + nt * 8 + (lane & 3) * 2;
            const float* d = acc[mt][nt];
            #pragma unroll
            for (int hrow = 0; hrow < 2; hrow++) {
                float v0 = fmaxf(d[hrow * 2 + 0], 0.f);
                float v1 = fmaxf(d[hrow * 2 + 1], 0.f);
                int rr = r0 + hrow * 8;
                if (OUT_SPLIT) {
                    __half h0, l0, h1, l1;
                    split16(v0, h0, l0);
                    split16(v1, h1, l1);
                    *(__half2*)(Xhi + (size_t)rr * E_DIM + c0) =
                        __halves2half2(h0, h1);
                    *(__half2*)(Xlo + (size_t)rr * E_DIM + c0) =
                        __halves2half2(l0, l1);
                } else {
                    *(float2*)(C + (size_t)rr * E_DIM + c0) =
                        make_float2(v0, v1);
                }
            }
        }
}

// ===========================================================================
// Launch
// ===========================================================================
extern "C" void kernel_launch(void* const* d_in, const int* in_sizes, int n_in,
                              void* d_out, int out_size)
{
    const float* Lemb = (const float*)d_in[0];
    const float* Xpt  = (const float*)d_in[1];
    const float* Wpt  = (const float*)d_in[2];
    const float* W0   = (const float*)d_in[3];
    const float* W1   = (const float*)d_in[4];
    float* out = (float*)d_out;

    float *Z, *S;
    __half *Zh, *Phi, *Plo, *Ahi, *Alo, *Whi, *Wlo, *Thi, *Tlo;
    cudaGetSymbolAddress((void**)&Z,   g_Z);
    cudaGetSymbolAddress((void**)&Zh,  g_Zh);
    cudaGetSymbolAddress((void**)&S,   g_S);
    cudaGetSymbolAddress((void**)&Phi, g_Phi);
    cudaGetSymbolAddress((void**)&Plo, g_Plo);
    cudaGetSymbolAddress((void**)&Ahi, g_Ahi);
    cudaGetSymbolAddress((void**)&Alo, g_Alo);
    cudaGetSymbolAddress((void**)&Whi, g_Whi);
    cudaGetSymbolAddress((void**)&Wlo, g_Wlo);
    cudaGetSymbolAddress((void**)&Thi, g_Thi);
    cudaGetSymbolAddress((void**)&Tlo, g_Tlo);

    cudaFuncSetAttribute(zzt_mma, cudaFuncAttributeMaxDynamicSharedMemorySize,
                         ZZT_SMEM);
    cudaFuncSetAttribute(split_mma, cudaFuncAttributeMaxDynamicSharedMemorySize,
                         GCN_SMEM);
    cudaFuncSetAttribute(gcn_mma<0>, cudaFuncAttributeMaxDynamicSharedMemorySize,
                         GCN_SMEM);
    cudaFuncSetAttribute(gcn_mma<1>, cudaFuncAttributeMaxDynamicSharedMemorySize,
                         GCN_SMEM);

    zero_cnt<<<1, 1>>>();

    // 1) Z fp32 + Zh fp16
    compute_z<<<L_DIM, 512>>>(Xpt, Wpt, Z, Zh);

    // 2) scores = Z Z^T (single-pass fp16 mma), band scan fused
    zzt_mma<<<dim3(16, 16), 256, ZZT_SMEM>>>(Zh, S);

    // 3) exact fp32 fixup of near-threshold entries (CTA per entry)
    fixup_band<<<1024, 128>>>(Z, S);

    // 4) adj = softmax(threshold(scores)) -> fp16 hi/lo
    masked_softmax<<<L_DIM, 256>>>(S, Phi, Plo);

    // 5) input conversions for layer 1
    split_rows<<<(L_DIM * E_DIM + 255) / 256, 256>>>(Lemb, Ahi, Alo,
                                                     L_DIM * E_DIM);
    conv_wt<<<dim3(16, 16), 256>>>(W0, Whi, Wlo);

    // 6) T0t = (Lemb @ W0)^T fp16 hi/lo
    split_mma<<<dim3(E_DIM / 64, L_DIM / 128), 256, GCN_SMEM>>>(
        Ahi, Alo, Whi, Wlo, Thi, Tlo);

    // 7) X1 = relu(adj @ T0) -> fp16 hi/lo (row-major, feeds layer 2)
    gcn_mma<1><<<dim3(E_DIM / 64, L_DIM / 128), 256, GCN_SMEM>>>(
        Phi, Plo, Thi, Tlo, nullptr, Ahi, Alo);

    // 8) layer-2 weight conversion + T1t = (X1 @ W1)^T
    conv_wt<<<dim3(16, 16), 256>>>(W1, Whi, Wlo);
    split_mma<<<dim3(E_DIM / 64, L_DIM / 128), 256, GCN_SMEM>>>(
        Ahi, Alo, Whi, Wlo, Thi, Tlo);

    // 9) out = relu(adj @ T1) fp32
    gcn_mma<0><<<dim3(E_DIM / 64, L_DIM / 128), 256, GCN_SMEM>>>(
        Phi, Plo, Thi, Tlo, out, nullptr, nullptr);
}